// round 9
// baseline (speedup 1.0000x reference)
#include <cuda_runtime.h>
#include <cstdint>

typedef unsigned long long u64;

// ---- exact f32 tap tables (computed on device in k_init) ----
__device__ float d_kA[64], d_kB[64], d_kC[64];   // psp taps tau = 1, 2, 4
__device__ float d_r1[32], d_r2[32], d_r3[32];   // refractory taps per layer

// ---- scratch (device globals; allocations forbidden) ----
__device__ __align__(256) float g_psp1[8 * 2 * 64 * 64 * 64];      // [b][c][y][x][t]
__device__ __align__(256) u64 g_s1[8 * 8 * 64 * 64];               // layer1 spike bits
__device__ __align__(256) u64 g_s2[8 * 2 * 128 * 128];             // layer2 spike bits
__device__ __align__(256) float g_psp3[16ull * 64 * 128 * 128];    // [(b*2+c)][t][y*128+x]

// ============================================================
// tap tables (f32; R4==R5 proved exp-impl insensitivity)
// ============================================================
__global__ void k_init()
{
    int d = threadIdx.x;   // 0..63
    float df = (float)d;
    float aA = df;
    float aB = __fmul_rn(df, 0.5f);
    float aC = __fmul_rn(df, 0.25f);
    float kA = __fmul_rn(aA, expf(__fsub_rn(1.0f, aA)));
    float kB = __fmul_rn(aB, expf(__fsub_rn(1.0f, aB)));
    float kC = __fmul_rn(aC, expf(__fsub_rn(1.0f, aC)));
    d_kA[d] = kA; d_kB[d] = kB; d_kC[d] = kC;
    if (d < 32) {
        d_r1[d] = __fmul_rn(-60.0f, kA);
        d_r2[d] = __fmul_rn(-100.0f, kB);
        d_r3[d] = __fmul_rn(-200.0f, kC);
    }
}

// Sum psp taps over spike history, OLDEST spike first (ascending t_x), f32 adds.
__device__ __forceinline__ float tapsum(u64 bits, const float* __restrict__ k, int t)
{
    u64 m = bits & ((t >= 63) ? ~0ull : ((1ull << (t + 1)) - 1ull));
    float acc = 0.f;
    while (m) {
        int i = __ffsll((long long)m) - 1;
        acc = __fadd_rn(acc, k[t - i]);
        m &= m - 1;
    }
    return acc;
}

// Refractory ref[0](t): fold over spikes t_x in [t-32, t-1], oldest first, r[t-1-t_x].
// lax.scan fixes this order semantically -> exact f32 replication.
__device__ __forceinline__ float refr(u64 h, const float* __restrict__ r, int t)
{
    if (t == 0) return 0.f;
    u64 hi = (1ull << t) - 1ull;
    u64 lo = (t >= 33) ? ((1ull << (t - 32)) - 1ull) : 0ull;
    u64 m = h & hi & ~lo;
    float acc = 0.f;
    while (m) {
        int i = __ffsll((long long)m) - 1;
        acc = __fadd_rn(acc, r[t - 1 - i]);
        m &= m - 1;
    }
    return acc;
}

// ============================================================
// K1: psp1 (tau=1) exact f32 tap-fold per neuron row
// ============================================================
__global__ void k_psp1(const float* __restrict__ in)
{
    __shared__ float kA[64];
    if (threadIdx.x < 64) kA[threadIdx.x] = d_kA[threadIdx.x];
    __syncthreads();

    int r = blockIdx.x * blockDim.x + threadIdx.x;     // 65536 rows (b,c,y,x)
    const float4* src = (const float4*)(in + (size_t)r * 64);
    float4* dst = (float4*)(g_psp1 + (size_t)r * 64);

    u64 bits = 0ull;
#pragma unroll
    for (int i = 0; i < 16; i++) {
        float4 x = src[i];
        bits |= ((u64)(x.x > 0.5f)) << (4 * i + 0);
        bits |= ((u64)(x.y > 0.5f)) << (4 * i + 1);
        bits |= ((u64)(x.z > 0.5f)) << (4 * i + 2);
        bits |= ((u64)(x.w > 0.5f)) << (4 * i + 3);
    }
#pragma unroll 1
    for (int tp = 0; tp < 16; tp++) {
        float4 y;
        y.x = tapsum(bits, kA, 4 * tp + 0);
        y.y = tapsum(bits, kA, 4 * tp + 1);
        y.z = tapsum(bits, kA, 4 * tp + 2);
        y.w = tapsum(bits, kA, 4 * tp + 3);
        dst[tp] = y;
    }
}

// ============================================================
// K2: layer1 = conv5x5(psp1) with DOUBLE accumulation (f32 x f32 -> f64 exact
//     products; order-independent true sum) + f32 refractory, double compare
// ============================================================
#define TPAD 68
__global__ void __launch_bounds__(256, 2) k_layer1(const float* __restrict__ w1)
{
    __shared__ float r1s[32];
    __shared__ double wsd[8][50];    // exact doubles of w1
    extern __shared__ float sm[];    // [2][12][12][TPAD]
    int tid = threadIdx.x;
    if (tid < 32) r1s[tid] = d_r1[tid];
    for (int i = tid; i < 400; i += 256)
        wsd[i / 50][i % 50] = (double)w1[i];

    int b = blockIdx.z, ty = blockIdx.y, tx = blockIdx.x;
    int gy0 = ty * 8 - 2, gx0 = tx * 8 - 2;

    for (int rr = tid; rr < 288 * 16; rr += 256) {
        int chunk = rr & 15, row = rr >> 4;
        int c = row / 144, rem = row - c * 144;
        int ly = rem / 12, lx = rem - ly * 12;
        int gy = gy0 + ly, gx = gx0 + lx;
        float4 v = make_float4(0.f, 0.f, 0.f, 0.f);
        if ((unsigned)gy < 64u && (unsigned)gx < 64u)
            v = *(const float4*)&g_psp1[(((size_t)((b * 2 + c) * 64 + gy) * 64 + gx) << 6) + chunk * 4];
        float* d = &sm[((c * 12 + ly) * 12 + lx) * TPAD + chunk * 4];
        d[0] = v.x; d[1] = v.y; d[2] = v.z; d[3] = v.w;
    }
    __syncthreads();

    int og = tid & 3, pix = tid >> 2;
    int yl = pix >> 3, xl = pix & 7;
    int o0 = og * 2, o1 = og * 2 + 1;

    const float* basep = &sm[(yl * 12 + xl) * TPAD];
    u64 h0 = 0ull, h1 = 0ull;

#pragma unroll 1
    for (int t = 0; t < 64; t++) {
        double a0 = 0.0, a1 = 0.0;
#pragma unroll
        for (int ky = 0; ky < 5; ky++)
#pragma unroll
            for (int kx = 0; kx < 5; kx++)
#pragma unroll
                for (int c = 0; c < 2; c++) {
                    const int k = c * 25 + ky * 5 + kx;
                    double xd = (double)basep[(c * 144 + ky * 12 + kx) * TPAD + t];
                    a0 = fma(wsd[o0][k], xd, a0);
                    a1 = fma(wsd[o1][k], xd, a1);
                }
        { double v = a0 + (double)refr(h0, r1s, t); if (v >= 30.0) h0 |= (1ull << t); }
        { double v = a1 + (double)refr(h1, r1s, t); if (v >= 30.0) h1 |= (1ull << t); }
    }
    int gy = ty * 8 + yl, gx = tx * 8 + xl;
    g_s1[((b * 8 + o0) * 64 + gy) * 64 + gx] = h0;
    g_s1[((b * 8 + o1) * 64 + gy) * 64 + gx] = h1;
}

// ============================================================
// K3: layer2 = deconv2x2( psp(s1, tau=2) ), dot in DOUBLE, f32 refractory,
//     double threshold compare (theta=50)
// ============================================================
__global__ void k_layer2(const float* __restrict__ w2g)
{
    __shared__ double w[64];
    __shared__ float kB[64], r2s[32];
    if (threadIdx.x < 64) { w[threadIdx.x] = (double)w2g[threadIdx.x]; kB[threadIdx.x] = d_kB[threadIdx.x]; }
    if (threadIdx.x < 32) r2s[threadIdx.x] = d_r2[threadIdx.x];
    __syncthreads();

    int tid0 = blockIdx.x * 128 + threadIdx.x;          // 32768 pixels
    int b = tid0 >> 12, rem = tid0 & 4095;
    int y = rem >> 6, x = rem & 63;

    u64 sw[8];
#pragma unroll
    for (int c = 0; c < 8; c++) sw[c] = g_s1[((b * 8 + c) * 64 + y) * 64 + x];

    u64 h[8];
#pragma unroll
    for (int n = 0; n < 8; n++) h[n] = 0ull;

#pragma unroll 1
    for (int t = 0; t < 64; t++) {
        double p2[8];
#pragma unroll
        for (int c = 0; c < 8; c++) p2[c] = (double)tapsum(sw[c], kB, t);
#pragma unroll
        for (int n = 0; n < 8; n++) {
            const int o = n >> 2, ij = n & 3;
            double z = 0.0;
#pragma unroll
            for (int c = 0; c < 8; c++)
                z = fma(p2[c], w[(c * 2 + o) * 4 + ij], z);
            double v = z + (double)refr(h[n], r2s, t);
            if (v >= 50.0) h[n] |= (1ull << t);
        }
    }
#pragma unroll
    for (int n = 0; n < 8; n++) {
        int o = n >> 2, i = (n >> 1) & 1, j = n & 1;
        g_s2[((b * 2 + o) * 128 + (2 * y + i)) * 128 + (2 * x + j)] = h[n];
    }
}

// ============================================================
// K4a: psp3 = psp(s2, tau=4) f32, dense, layout [(b*2+c)][t][y*128+x]
// ============================================================
__global__ void k_psp3()
{
    __shared__ float kC[64];
    if (threadIdx.x < 64) kC[threadIdx.x] = d_kC[threadIdx.x];
    __syncthreads();
    int idx = blockIdx.x * 256 + threadIdx.x;           // 16,777,216
    int yx = idx & 16383;
    int t = (idx >> 14) & 63;
    int bc = idx >> 20;
    g_psp3[idx] = tapsum(g_s2[bc * 16384 + yx], kC, t);
}

// ============================================================
// K4b: layer3 = conv3x3(psp3) in DOUBLE + f32 bilinear2x(psp1) skip
//      + f32 refractory, double compare (theta=100)
// ============================================================
__global__ void __launch_bounds__(256) k_layer3(const float* __restrict__ w3g,
                                                float* __restrict__ out)
{
    __shared__ double w[36];
    __shared__ float r3s[32];
    __shared__ float tile[2][18][18];
    if (threadIdx.x < 36) w[threadIdx.x] = (double)w3g[threadIdx.x];
    if (threadIdx.x < 32) r3s[threadIdx.x] = d_r3[threadIdx.x];

    int b = blockIdx.z;
    int ty0 = blockIdx.y * 16, tx0 = blockIdx.x * 16;
    int tid = threadIdx.x;
    int yl = tid >> 4, xl = tid & 15;
    int Y = ty0 + yl, X = tx0 + xl;

    bool eY = (Y == 0) || (Y == 127);
    bool eX = (X == 0) || (X == 127);
    int y0 = (Y == 0) ? 0 : ((Y - 1) >> 1);
    int y1 = (y0 + 1 > 63) ? 63 : y0 + 1;
    int x0 = (X == 0) ? 0 : ((X - 1) >> 1);
    int x1 = (x0 + 1 > 63) ? 63 : x0 + 1;
    float wy1 = (Y & 1) ? 0.25f : 0.75f, wy0 = 1.f - wy1;
    float wx1 = (X & 1) ? 0.25f : 0.75f, wx0 = 1.f - wx1;

    const float* pr[2][4];
#pragma unroll
    for (int c = 0; c < 2; c++) {
        const float* base = &g_psp1[(size_t)(b * 2 + c) * 64 * 64 * 64];
        pr[c][0] = base + ((size_t)y0 * 64 + x0) * 64;
        pr[c][1] = base + ((size_t)y1 * 64 + x0) * 64;
        pr[c][2] = base + ((size_t)y0 * 64 + x1) * 64;
        pr[c][3] = base + ((size_t)y1 * 64 + x1) * 64;
    }

    u64 h[2] = {0ull, 0ull};

#pragma unroll 1
    for (int t = 0; t < 64; t++) {
        __syncthreads();
        for (int i = tid; i < 648; i += 256) {
            int c = i / 324, rr = i - c * 324;
            int lyy = rr / 18, lxx = rr - lyy * 18;
            int gy = ty0 + lyy - 1, gx = tx0 + lxx - 1;
            float v = 0.f;
            if ((unsigned)gy < 128u && (unsigned)gx < 128u)
                v = g_psp3[((size_t)(b * 2 + c) * 64 + t) * 16384 + gy * 128 + gx];
            tile[c][lyy][lxx] = v;
        }
        __syncthreads();

        double acc0 = 0.0, acc1 = 0.0;
#pragma unroll
        for (int c = 0; c < 2; c++)
#pragma unroll
            for (int ky = 0; ky < 3; ky++)
#pragma unroll
                for (int kx = 0; kx < 3; kx++) {
                    double xd = (double)tile[c][yl + ky][xl + kx];
                    acc0 = fma(w[(0 * 2 + c) * 9 + ky * 3 + kx], xd, acc0);
                    acc1 = fma(w[(1 * 2 + c) * 9 + ky * 3 + kx], xd, acc1);
                }

#pragma unroll
        for (int o = 0; o < 2; o++) {
            float p00 = pr[o][0][t], p10 = pr[o][1][t];
            float p01 = pr[o][2][t], p11 = pr[o][3][t];
            float A = eY ? p00 : __fmaf_rn(wy1, p10, __fmul_rn(wy0, p00));
            float B = eY ? p01 : __fmaf_rn(wy1, p11, __fmul_rn(wy0, p01));
            float skip = eX ? A : __fmaf_rn(wx1, B, __fmul_rn(wx0, A));
            double v = (o ? acc1 : acc0) + (double)skip + (double)refr(h[o], r3s, t);
            if (v >= 100.0) h[o] |= (1ull << t);
        }
    }

#pragma unroll
    for (int o = 0; o < 2; o++) {
        float4* dst = (float4*)(out + ((size_t)((b * 2 + o) * 128 + Y) * 128 + X) * 64);
        u64 m = h[o];
#pragma unroll
        for (int k = 0; k < 16; k++) {
            float4 v;
            v.x = (float)((unsigned)((m >> (4 * k + 0)) & 1ull));
            v.y = (float)((unsigned)((m >> (4 * k + 1)) & 1ull));
            v.z = (float)((unsigned)((m >> (4 * k + 2)) & 1ull));
            v.w = (float)((unsigned)((m >> (4 * k + 3)) & 1ull));
            dst[k] = v;
        }
    }
}

extern "C" void kernel_launch(void* const* d_in, const int* in_sizes, int n_in,
                              void* d_out, int out_size)
{
    const float* in = (const float*)d_in[0];
    const float* w1 = (const float*)d_in[1];
    const float* w2 = (const float*)d_in[2];
    const float* w3 = (const float*)d_in[3];
    float* out = (float*)d_out;

    cudaFuncSetAttribute(k_layer1, cudaFuncAttributeMaxDynamicSharedMemorySize,
                         2 * 144 * TPAD * 4);

    k_init<<<1, 64>>>();
    k_psp1<<<256, 256>>>(in);
    dim3 g1(8, 8, 8);
    k_layer1<<<g1, 256, 2 * 144 * TPAD * 4>>>(w1);
    k_layer2<<<256, 128>>>(w2);
    k_psp3<<<65536, 256>>>();
    dim3 g3(8, 8, 8);
    k_layer3<<<g3, 256>>>(w3, out);
}

// round 10
// speedup vs baseline: 2.0937x; 2.0937x over previous
#include <cuda_runtime.h>
#include <cstdint>

typedef unsigned long long u64;

// ---- exact f32 tap tables ----
__device__ float d_kA[64], d_kB[64], d_kC[64];   // psp taps tau = 1, 2, 4
__device__ float d_r1[32], d_r2[32], d_r3[32];   // refractory taps per layer

// ---- scratch (device globals; allocations forbidden) ----
__device__ __align__(256) float g_psp1[8 * 2 * 64 * 64 * 64];      // [b][c][y][x][t]
__device__ __align__(256) u64 g_s1[8 * 8 * 64 * 64];               // layer1 spike bits
__device__ __align__(256) u64 g_s2[8 * 2 * 128 * 128];             // layer2 spike bits
__device__ __align__(256) float g_pspX[16ull * 64 * 16384];        // psp2 [bc8][t][yx4096] then psp3 [bc2][t][yx16384]

// ============================================================
__global__ void k_init()
{
    int d = threadIdx.x;   // 0..63
    float df = (float)d;
    float aA = df;
    float aB = __fmul_rn(df, 0.5f);
    float aC = __fmul_rn(df, 0.25f);
    float kA = __fmul_rn(aA, expf(__fsub_rn(1.0f, aA)));
    float kB = __fmul_rn(aB, expf(__fsub_rn(1.0f, aB)));
    float kC = __fmul_rn(aC, expf(__fsub_rn(1.0f, aC)));
    d_kA[d] = kA; d_kB[d] = kB; d_kC[d] = kC;
    if (d < 32) {
        d_r1[d] = __fmul_rn(-60.0f, kA);
        d_r2[d] = __fmul_rn(-100.0f, kB);
        d_r3[d] = __fmul_rn(-200.0f, kC);
    }
}

// Refractory: fold over spikes t_x in [t-32, t-1], oldest first, of r[t-1-t_x]. (bit-exact, as R9)
__device__ __forceinline__ float refr(u64 h, const float* __restrict__ r, int t)
{
    if (t == 0) return 0.f;
    u64 hi = (1ull << t) - 1ull;
    u64 lo = (t >= 33) ? ((1ull << (t - 32)) - 1ull) : 0ull;
    u64 m = h & hi & ~lo;
    float acc = 0.f;
    while (m) {
        int i = __ffsll((long long)m) - 1;
        acc = __fadd_rn(acc, r[t - 1 - i]);
        m &= m - 1;
    }
    return acc;
}

// ============================================================
// Shifted-tap tables for vectorized psp fold.
// kpad[x] = (x>=64) ? k[x-64] : +0.   E[m]=(kpad[2m],kpad[2m+1]), O[m]=(kpad[2m+1],kpad[2m+2])
// Spike at time i adds k[t-i] to acc[t] for t>=i; for t<i it adds +0 (exact identity,
// all taps >= +0 and acc starts at +0, so acc is never -0). Per-t addition order is
// ascending spike time == R9's tapsum fold ==> BIT-IDENTICAL result.
// ============================================================
__device__ __forceinline__ void build_tables(const float* __restrict__ kk, u64* E, u64* O)
{
    for (int m = threadIdx.x; m < 64; m += blockDim.x) {
        float e0 = (2 * m - 64 >= 0) ? kk[2 * m - 64] : 0.f;
        float e1 = (2 * m - 63 >= 0) ? kk[2 * m - 63] : 0.f;
        float o1 = (2 * m - 62 >= 0) ? kk[2 * m - 62] : 0.f;
        E[m] = ((u64)__float_as_uint(e1) << 32) | (u64)__float_as_uint(e0);
        O[m] = ((u64)__float_as_uint(o1) << 32) | (u64)__float_as_uint(e1);
    }
}

__device__ __forceinline__ void psp_fold(u64 bits, const u64* __restrict__ E,
                                         const u64* __restrict__ O, u64* acc2)
{
    while (bits) {
        int i = __ffsll((long long)bits) - 1;
        bits &= bits - 1;
        const u64* base = (i & 1) ? (O + (31 - ((i - 1) >> 1))) : (E + (32 - (i >> 1)));
#pragma unroll
        for (int j = 0; j < 32; j++)
            asm("add.rn.f32x2 %0, %0, %1;" : "+l"(acc2[j]) : "l"(base[j]));
    }
}

// ============================================================
// K1: psp1 (tau=1) via shifted-tap vector fold; writes dense [b][c][y][x][t]
// ============================================================
__global__ void k_psp1(const float* __restrict__ in)
{
    __shared__ u64 E[64], O[64];
    build_tables(d_kA, E, O);
    __syncthreads();

    int r = blockIdx.x * 256 + threadIdx.x;     // 65536 rows
    const float4* src = (const float4*)(in + (size_t)r * 64);
    u64 bits = 0ull;
#pragma unroll
    for (int i = 0; i < 16; i++) {
        float4 x = src[i];
        bits |= ((u64)(x.x > 0.5f)) << (4 * i + 0);
        bits |= ((u64)(x.y > 0.5f)) << (4 * i + 1);
        bits |= ((u64)(x.z > 0.5f)) << (4 * i + 2);
        bits |= ((u64)(x.w > 0.5f)) << (4 * i + 3);
    }
    u64 acc2[32];
#pragma unroll
    for (int j = 0; j < 32; j++) acc2[j] = 0ull;
    psp_fold(bits, E, O, acc2);

    const float* a = (const float*)acc2;
    float4* dst = (float4*)(g_psp1 + (size_t)r * 64);
#pragma unroll
    for (int q = 0; q < 16; q++)
        dst[q] = make_float4(a[4 * q], a[4 * q + 1], a[4 * q + 2], a[4 * q + 3]);
}

// ============================================================
// K2: layer1 conv5x5 — f32x2 fast path + sound bound; f64 fallback in band
// (decision provably identical to R9's f64 chain)
// ============================================================
#define TPAD 68
__global__ void __launch_bounds__(256) k_layer1(const float* __restrict__ w1)
{
    __shared__ float r1s[32];
    extern __shared__ float sm[];    // [2][12][12][TPAD]
    int tid = threadIdx.x;
    if (tid < 32) r1s[tid] = d_r1[tid];

    int b = blockIdx.z, ty = blockIdx.y, tx = blockIdx.x;
    int gy0 = ty * 8 - 2, gx0 = tx * 8 - 2;
    for (int rr = tid; rr < 288 * 16; rr += 256) {
        int chunk = rr & 15, row = rr >> 4;
        int c = row / 144, rem = row - c * 144;
        int ly = rem / 12, lx = rem - ly * 12;
        int gy = gy0 + ly, gx = gx0 + lx;
        float4 v = make_float4(0.f, 0.f, 0.f, 0.f);
        if ((unsigned)gy < 64u && (unsigned)gx < 64u)
            v = *(const float4*)&g_psp1[(((size_t)((b * 2 + c) * 64 + gy) * 64 + gx) << 6) + chunk * 4];
        float* d = &sm[((c * 12 + ly) * 12 + lx) * TPAD + chunk * 4];
        d[0] = v.x; d[1] = v.y; d[2] = v.z; d[3] = v.w;
    }
    __syncthreads();

    int og = tid & 3, pix = tid >> 2;
    int yl = pix >> 3, xl = pix & 7;
    int o0 = og * 2, o1 = og * 2 + 1;

    float wa[50], wb[50];
    float Wa = 0.f, Wb = 0.f;
#pragma unroll
    for (int k = 0; k < 50; k++) {
        wa[k] = __ldg(&w1[o0 * 50 + k]);
        wb[k] = __ldg(&w1[o1 * 50 + k]);
        Wa += fabsf(wa[k]);
        Wb += fabsf(wb[k]);
    }
    // |f32 chain - exact| <= 50 * 2^-24 * (Sum|w| * 2.6) * 1.05  (psp1 <= 2.51)
    double Ba = (double)(Wa * 8.2e-6f);
    double Bb = (double)(Wb * 8.2e-6f);

    const float* basep = &sm[(yl * 12 + xl) * TPAD];
    u64 h0 = 0ull, h1 = 0ull;

#define DECIDE(h, uval, tt, oo, BB) do {                                          \
    float rf_ = refr(h, r1s, tt);                                                 \
    double v_ = (double)(uval) + (double)rf_ - 30.0;                              \
    bool s_;                                                                      \
    if (v_ > (BB)) s_ = true;                                                     \
    else if (v_ < -(BB)) s_ = false;                                              \
    else {                                                                        \
        double a_ = 0.0;                                                          \
        _Pragma("unroll 1")                                                       \
        for (int kk_ = 0; kk_ < 50; kk_++) {                                      \
            int c_ = kk_ / 25, rm_ = kk_ % 25, ky_ = rm_ / 5, kx_ = rm_ % 5;      \
            a_ = fma((double)__ldg(&w1[(oo) * 50 + kk_]),                         \
                     (double)basep[(c_ * 144 + ky_ * 12 + kx_) * TPAD + (tt)], a_);\
        }                                                                         \
        s_ = (a_ + (double)rf_ >= 30.0);                                          \
    }                                                                             \
    if (s_) h |= (1ull << (tt));                                                  \
} while (0)

#pragma unroll 1
    for (int tp = 0; tp < 32; tp++) {
        u64 acc0 = 0ull, acc1 = 0ull;
        const u64* xp = (const u64*)(basep + 2 * tp);
#pragma unroll
        for (int ky = 0; ky < 5; ky++)
#pragma unroll
            for (int kx = 0; kx < 5; kx++)
#pragma unroll
                for (int c = 0; c < 2; c++) {
                    const int k = c * 25 + ky * 5 + kx;
                    u64 x2 = xp[(c * 144 + ky * 12 + kx) * (TPAD / 2)];
                    u64 wv;
                    asm("mov.b64 %0, {%1, %1};" : "=l"(wv) : "f"(wa[k]));
                    asm("fma.rn.f32x2 %0, %1, %2, %0;" : "+l"(acc0) : "l"(wv), "l"(x2));
                    asm("mov.b64 %0, {%1, %1};" : "=l"(wv) : "f"(wb[k]));
                    asm("fma.rn.f32x2 %0, %1, %2, %0;" : "+l"(acc1) : "l"(wv), "l"(x2));
                }
        float ua0, ua1, ub0, ub1;
        asm("mov.b64 {%0, %1}, %2;" : "=f"(ua0), "=f"(ua1) : "l"(acc0));
        asm("mov.b64 {%0, %1}, %2;" : "=f"(ub0), "=f"(ub1) : "l"(acc1));
        int t = 2 * tp;
        DECIDE(h0, ua0, t,     o0, Ba);
        DECIDE(h0, ua1, t + 1, o0, Ba);
        DECIDE(h1, ub0, t,     o1, Bb);
        DECIDE(h1, ub1, t + 1, o1, Bb);
    }
#undef DECIDE
    int gy = ty * 8 + yl, gx = tx * 8 + xl;
    g_s1[((b * 8 + o0) * 64 + gy) * 64 + gx] = h0;
    g_s1[((b * 8 + o1) * 64 + gy) * 64 + gx] = h1;
}

// ============================================================
// K3a: psp2 = psp(s1, tau=2) via shifted-tap fold -> g_pspX [bc8][t][yx4096]
// ============================================================
__global__ void k_psp2()
{
    __shared__ u64 E[64], O[64];
    build_tables(d_kB, E, O);
    __syncthreads();

    int idx = blockIdx.x * 256 + threadIdx.x;   // 262144 = [b*8+c][y*64+x]
    u64 bits = g_s1[idx];
    u64 acc2[32];
#pragma unroll
    for (int j = 0; j < 32; j++) acc2[j] = 0ull;
    psp_fold(bits, E, O, acc2);

    int bc = idx >> 12, yx = idx & 4095;
    const float* a = (const float*)acc2;
#pragma unroll
    for (int t = 0; t < 64; t++)
        g_pspX[((size_t)bc * 64 + t) * 4096 + yx] = a[t];
}

// ============================================================
// K3b: layer2 deconv dot in f64 over precomputed psp2 + exact LIF (as R9)
// ============================================================
__global__ void k_layer2(const float* __restrict__ w2g)
{
    __shared__ double w[64];
    __shared__ float r2s[32];
    if (threadIdx.x < 64) w[threadIdx.x] = (double)w2g[threadIdx.x];
    if (threadIdx.x < 32) r2s[threadIdx.x] = d_r2[threadIdx.x];
    __syncthreads();

    int tid0 = blockIdx.x * 128 + threadIdx.x;  // 32768 pixels
    int b = tid0 >> 12, yx = tid0 & 4095;
    int y = yx >> 6, x = yx & 63;

    u64 h[8];
#pragma unroll
    for (int n = 0; n < 8; n++) h[n] = 0ull;

#pragma unroll 1
    for (int t = 0; t < 64; t++) {
        double p2[8];
#pragma unroll
        for (int c = 0; c < 8; c++)
            p2[c] = (double)__ldg(&g_pspX[((size_t)(b * 8 + c) * 64 + t) * 4096 + yx]);
#pragma unroll
        for (int n = 0; n < 8; n++) {
            const int o = n >> 2, ij = n & 3;
            double z = 0.0;
#pragma unroll
            for (int c = 0; c < 8; c++)
                z = fma(p2[c], w[(c * 2 + o) * 4 + ij], z);
            double v = z + (double)refr(h[n], r2s, t);
            if (v >= 50.0) h[n] |= (1ull << t);
        }
    }
#pragma unroll
    for (int n = 0; n < 8; n++) {
        int o = n >> 2, i = (n >> 1) & 1, j = n & 1;
        g_s2[((b * 2 + o) * 128 + (2 * y + i)) * 128 + (2 * x + j)] = h[n];
    }
}

// ============================================================
// K4a: psp3 = psp(s2, tau=4) via shifted-tap fold -> g_pspX [bc2][t][yx16384]
// ============================================================
__global__ void k_psp3()
{
    __shared__ u64 E[64], O[64];
    build_tables(d_kC, E, O);
    __syncthreads();

    int idx = blockIdx.x * 256 + threadIdx.x;   // 262144 = [b*2+o][yx16384]
    u64 bits = g_s2[idx];
    u64 acc2[32];
#pragma unroll
    for (int j = 0; j < 32; j++) acc2[j] = 0ull;
    psp_fold(bits, E, O, acc2);

    int bc = idx >> 14, yx = idx & 16383;
    const float* a = (const float*)acc2;
#pragma unroll
    for (int t = 0; t < 64; t++)
        g_pspX[((size_t)bc * 64 + t) * 16384 + yx] = a[t];
}

// ============================================================
// K4b: layer3 = conv3x3(psp3) in f64 + f32 bilinear skip + exact LIF (as R9)
// ============================================================
__global__ void __launch_bounds__(256) k_layer3(const float* __restrict__ w3g,
                                                float* __restrict__ out)
{
    __shared__ double w[36];
    __shared__ float r3s[32];
    __shared__ float tile[2][18][18];
    if (threadIdx.x < 36) w[threadIdx.x] = (double)w3g[threadIdx.x];
    if (threadIdx.x < 32) r3s[threadIdx.x] = d_r3[threadIdx.x];

    int b = blockIdx.z;
    int ty0 = blockIdx.y * 16, tx0 = blockIdx.x * 16;
    int tid = threadIdx.x;
    int yl = tid >> 4, xl = tid & 15;
    int Y = ty0 + yl, X = tx0 + xl;

    bool eY = (Y == 0) || (Y == 127);
    bool eX = (X == 0) || (X == 127);
    int y0 = (Y == 0) ? 0 : ((Y - 1) >> 1);
    int y1 = (y0 + 1 > 63) ? 63 : y0 + 1;
    int x0 = (X == 0) ? 0 : ((X - 1) >> 1);
    int x1 = (x0 + 1 > 63) ? 63 : x0 + 1;
    float wy1 = (Y & 1) ? 0.25f : 0.75f, wy0 = 1.f - wy1;
    float wx1 = (X & 1) ? 0.25f : 0.75f, wx0 = 1.f - wx1;

    const float* pr[2][4];
#pragma unroll
    for (int c = 0; c < 2; c++) {
        const float* base = &g_psp1[(size_t)(b * 2 + c) * 64 * 64 * 64];
        pr[c][0] = base + ((size_t)y0 * 64 + x0) * 64;
        pr[c][1] = base + ((size_t)y1 * 64 + x0) * 64;
        pr[c][2] = base + ((size_t)y0 * 64 + x1) * 64;
        pr[c][3] = base + ((size_t)y1 * 64 + x1) * 64;
    }

    u64 h[2] = {0ull, 0ull};

#pragma unroll 1
    for (int t = 0; t < 64; t++) {
        __syncthreads();
        for (int i = tid; i < 648; i += 256) {
            int c = i / 324, rr = i - c * 324;
            int lyy = rr / 18, lxx = rr - lyy * 18;
            int gy = ty0 + lyy - 1, gx = tx0 + lxx - 1;
            float v = 0.f;
            if ((unsigned)gy < 128u && (unsigned)gx < 128u)
                v = g_pspX[((size_t)(b * 2 + c) * 64 + t) * 16384 + gy * 128 + gx];
            tile[c][lyy][lxx] = v;
        }
        __syncthreads();

        double acc0 = 0.0, acc1 = 0.0;
#pragma unroll
        for (int c = 0; c < 2; c++)
#pragma unroll
            for (int ky = 0; ky < 3; ky++)
#pragma unroll
                for (int kx = 0; kx < 3; kx++) {
                    double xd = (double)tile[c][yl + ky][xl + kx];
                    acc0 = fma(w[(0 * 2 + c) * 9 + ky * 3 + kx], xd, acc0);
                    acc1 = fma(w[(1 * 2 + c) * 9 + ky * 3 + kx], xd, acc1);
                }

#pragma unroll
        for (int o = 0; o < 2; o++) {
            float p00 = pr[o][0][t], p10 = pr[o][1][t];
            float p01 = pr[o][2][t], p11 = pr[o][3][t];
            float A = eY ? p00 : __fmaf_rn(wy1, p10, __fmul_rn(wy0, p00));
            float B = eY ? p01 : __fmaf_rn(wy1, p11, __fmul_rn(wy0, p01));
            float skip = eX ? A : __fmaf_rn(wx1, B, __fmul_rn(wx0, A));
            double v = (o ? acc1 : acc0) + (double)skip + (double)refr(h[o], r3s, t);
            if (v >= 100.0) h[o] |= (1ull << t);
        }
    }

#pragma unroll
    for (int o = 0; o < 2; o++) {
        float4* dst = (float4*)(out + ((size_t)((b * 2 + o) * 128 + Y) * 128 + X) * 64);
        u64 m = h[o];
#pragma unroll
        for (int k = 0; k < 16; k++) {
            float4 v;
            v.x = (float)((unsigned)((m >> (4 * k + 0)) & 1ull));
            v.y = (float)((unsigned)((m >> (4 * k + 1)) & 1ull));
            v.z = (float)((unsigned)((m >> (4 * k + 2)) & 1ull));
            v.w = (float)((unsigned)((m >> (4 * k + 3)) & 1ull));
            dst[k] = v;
        }
    }
}

extern "C" void kernel_launch(void* const* d_in, const int* in_sizes, int n_in,
                              void* d_out, int out_size)
{
    const float* in = (const float*)d_in[0];
    const float* w1 = (const float*)d_in[1];
    const float* w2 = (const float*)d_in[2];
    const float* w3 = (const float*)d_in[3];
    float* out = (float*)d_out;

    cudaFuncSetAttribute(k_layer1, cudaFuncAttributeMaxDynamicSharedMemorySize,
                         2 * 144 * TPAD * 4);

    k_init<<<1, 64>>>();
    k_psp1<<<256, 256>>>(in);
    dim3 g1(8, 8, 8);
    k_layer1<<<g1, 256, 2 * 144 * TPAD * 4>>>(w1);
    k_psp2<<<1024, 256>>>();
    k_layer2<<<256, 128>>>(w2);
    k_psp3<<<1024, 256>>>();
    dim3 g3(8, 8, 8);
    k_layer3<<<g3, 256>>>(w3, out);
}

// round 11
// speedup vs baseline: 3.5306x; 1.6863x over previous
#include <cuda_runtime.h>
#include <cstdint>

typedef unsigned long long u64;

// ---- exact f32 tap tables ----
__device__ float d_kA[64], d_kB[64], d_kC[64];   // psp taps tau = 1, 2, 4
__device__ float d_r1[32], d_r2[32], d_r3[32];   // refractory taps per layer

// ---- scratch (device globals; allocations forbidden) ----
__device__ __align__(256) float g_psp1[8 * 2 * 64 * 64 * 64];      // [b][c][y][x][t]
__device__ __align__(256) u64 g_s1[8 * 8 * 64 * 64];               // layer1 spike bits
__device__ __align__(256) u64 g_s2[8 * 2 * 128 * 128];             // layer2 spike bits
__device__ __align__(256) float g_pspX[16ull * 64 * 16384];        // psp2 [bc8][t][yx4096] then psp3 [bc2][t][yx16384]

// ============================================================
__global__ void k_init()
{
    int d = threadIdx.x;   // 0..63
    float df = (float)d;
    float aA = df;
    float aB = __fmul_rn(df, 0.5f);
    float aC = __fmul_rn(df, 0.25f);
    float kA = __fmul_rn(aA, expf(__fsub_rn(1.0f, aA)));
    float kB = __fmul_rn(aB, expf(__fsub_rn(1.0f, aB)));
    float kC = __fmul_rn(aC, expf(__fsub_rn(1.0f, aC)));
    d_kA[d] = kA; d_kB[d] = kB; d_kC[d] = kC;
    if (d < 32) {
        d_r1[d] = __fmul_rn(-60.0f, kA);
        d_r2[d] = __fmul_rn(-100.0f, kB);
        d_r3[d] = __fmul_rn(-200.0f, kC);
    }
}

// Refractory: fold over spikes t_x in [t-32, t-1], oldest first, of r[t-1-t_x]. (bit-exact)
__device__ __forceinline__ float refr(u64 h, const float* __restrict__ r, int t)
{
    if (t == 0) return 0.f;
    u64 hi = (1ull << t) - 1ull;
    u64 lo = (t >= 33) ? ((1ull << (t - 32)) - 1ull) : 0ull;
    u64 m = h & hi & ~lo;
    float acc = 0.f;
    while (m) {
        int i = __ffsll((long long)m) - 1;
        acc = __fadd_rn(acc, r[t - 1 - i]);
        m &= m - 1;
    }
    return acc;
}

// ============================================================
// Shifted-tap tables for vectorized psp fold (bit-identical to serial tapsum).
// ============================================================
__device__ __forceinline__ void build_tables(const float* __restrict__ kk, u64* E, u64* O)
{
    for (int m = threadIdx.x; m < 64; m += blockDim.x) {
        float e0 = (2 * m - 64 >= 0) ? kk[2 * m - 64] : 0.f;
        float e1 = (2 * m - 63 >= 0) ? kk[2 * m - 63] : 0.f;
        float o1 = (2 * m - 62 >= 0) ? kk[2 * m - 62] : 0.f;
        E[m] = ((u64)__float_as_uint(e1) << 32) | (u64)__float_as_uint(e0);
        O[m] = ((u64)__float_as_uint(o1) << 32) | (u64)__float_as_uint(e1);
    }
}

__device__ __forceinline__ void psp_fold(u64 bits, const u64* __restrict__ E,
                                         const u64* __restrict__ O, u64* acc2)
{
    while (bits) {
        int i = __ffsll((long long)bits) - 1;
        bits &= bits - 1;
        const u64* base = (i & 1) ? (O + (31 - ((i - 1) >> 1))) : (E + (32 - (i >> 1)));
#pragma unroll
        for (int j = 0; j < 32; j++)
            asm("add.rn.f32x2 %0, %0, %1;" : "+l"(acc2[j]) : "l"(base[j]));
    }
}

// ============================================================
// K1: psp1 (tau=1) via shifted-tap vector fold; writes dense [b][c][y][x][t]
// ============================================================
__global__ void k_psp1(const float* __restrict__ in)
{
    __shared__ u64 E[64], O[64];
    build_tables(d_kA, E, O);
    __syncthreads();

    int r = blockIdx.x * 256 + threadIdx.x;     // 65536 rows
    const float4* src = (const float4*)(in + (size_t)r * 64);
    u64 bits = 0ull;
#pragma unroll
    for (int i = 0; i < 16; i++) {
        float4 x = src[i];
        bits |= ((u64)(x.x > 0.5f)) << (4 * i + 0);
        bits |= ((u64)(x.y > 0.5f)) << (4 * i + 1);
        bits |= ((u64)(x.z > 0.5f)) << (4 * i + 2);
        bits |= ((u64)(x.w > 0.5f)) << (4 * i + 3);
    }
    u64 acc2[32];
#pragma unroll
    for (int j = 0; j < 32; j++) acc2[j] = 0ull;
    psp_fold(bits, E, O, acc2);

    const float* a = (const float*)acc2;
    float4* dst = (float4*)(g_psp1 + (size_t)r * 64);
#pragma unroll
    for (int q = 0; q < 16; q++)
        dst[q] = make_float4(a[4 * q], a[4 * q + 1], a[4 * q + 2], a[4 * q + 3]);
}

// ============================================================
// K2: layer1 conv5x5 — f32x2 fast path + sound bound; f64 fallback in band
// ============================================================
#define TPAD 68
__global__ void __launch_bounds__(256) k_layer1(const float* __restrict__ w1)
{
    __shared__ float r1s[32];
    extern __shared__ float sm[];    // [2][12][12][TPAD]
    int tid = threadIdx.x;
    if (tid < 32) r1s[tid] = d_r1[tid];

    int b = blockIdx.z, ty = blockIdx.y, tx = blockIdx.x;
    int gy0 = ty * 8 - 2, gx0 = tx * 8 - 2;
    for (int rr = tid; rr < 288 * 16; rr += 256) {
        int chunk = rr & 15, row = rr >> 4;
        int c = row / 144, rem = row - c * 144;
        int ly = rem / 12, lx = rem - ly * 12;
        int gy = gy0 + ly, gx = gx0 + lx;
        float4 v = make_float4(0.f, 0.f, 0.f, 0.f);
        if ((unsigned)gy < 64u && (unsigned)gx < 64u)
            v = *(const float4*)&g_psp1[(((size_t)((b * 2 + c) * 64 + gy) * 64 + gx) << 6) + chunk * 4];
        float* d = &sm[((c * 12 + ly) * 12 + lx) * TPAD + chunk * 4];
        d[0] = v.x; d[1] = v.y; d[2] = v.z; d[3] = v.w;
    }
    __syncthreads();

    int og = tid & 3, pix = tid >> 2;
    int yl = pix >> 3, xl = pix & 7;
    int o0 = og * 2, o1 = og * 2 + 1;

    float wa[50], wb[50];
    float Wa = 0.f, Wb = 0.f;
#pragma unroll
    for (int k = 0; k < 50; k++) {
        wa[k] = __ldg(&w1[o0 * 50 + k]);
        wb[k] = __ldg(&w1[o1 * 50 + k]);
        Wa += fabsf(wa[k]);
        Wb += fabsf(wb[k]);
    }
    double Ba = (double)(Wa * 8.2e-6f);
    double Bb = (double)(Wb * 8.2e-6f);

    const float* basep = &sm[(yl * 12 + xl) * TPAD];
    u64 h0 = 0ull, h1 = 0ull;

#define DECIDE(h, uval, tt, oo, BB) do {                                          \
    float rf_ = refr(h, r1s, tt);                                                 \
    double v_ = (double)(uval) + (double)rf_ - 30.0;                              \
    bool s_;                                                                      \
    if (v_ > (BB)) s_ = true;                                                     \
    else if (v_ < -(BB)) s_ = false;                                              \
    else {                                                                        \
        double a_ = 0.0;                                                          \
        _Pragma("unroll 1")                                                       \
        for (int kk_ = 0; kk_ < 50; kk_++) {                                      \
            int c_ = kk_ / 25, rm_ = kk_ % 25, ky_ = rm_ / 5, kx_ = rm_ % 5;      \
            a_ = fma((double)__ldg(&w1[(oo) * 50 + kk_]),                         \
                     (double)basep[(c_ * 144 + ky_ * 12 + kx_) * TPAD + (tt)], a_);\
        }                                                                         \
        s_ = (a_ + (double)rf_ >= 30.0);                                          \
    }                                                                             \
    if (s_) h |= (1ull << (tt));                                                  \
} while (0)

#pragma unroll 1
    for (int tp = 0; tp < 32; tp++) {
        u64 acc0 = 0ull, acc1 = 0ull;
        const u64* xp = (const u64*)(basep + 2 * tp);
#pragma unroll
        for (int ky = 0; ky < 5; ky++)
#pragma unroll
            for (int kx = 0; kx < 5; kx++)
#pragma unroll
                for (int c = 0; c < 2; c++) {
                    const int k = c * 25 + ky * 5 + kx;
                    u64 x2 = xp[(c * 144 + ky * 12 + kx) * (TPAD / 2)];
                    u64 wv;
                    asm("mov.b64 %0, {%1, %1};" : "=l"(wv) : "f"(wa[k]));
                    asm("fma.rn.f32x2 %0, %1, %2, %0;" : "+l"(acc0) : "l"(wv), "l"(x2));
                    asm("mov.b64 %0, {%1, %1};" : "=l"(wv) : "f"(wb[k]));
                    asm("fma.rn.f32x2 %0, %1, %2, %0;" : "+l"(acc1) : "l"(wv), "l"(x2));
                }
        float ua0, ua1, ub0, ub1;
        asm("mov.b64 {%0, %1}, %2;" : "=f"(ua0), "=f"(ua1) : "l"(acc0));
        asm("mov.b64 {%0, %1}, %2;" : "=f"(ub0), "=f"(ub1) : "l"(acc1));
        int t = 2 * tp;
        DECIDE(h0, ua0, t,     o0, Ba);
        DECIDE(h0, ua1, t + 1, o0, Ba);
        DECIDE(h1, ub0, t,     o1, Bb);
        DECIDE(h1, ub1, t + 1, o1, Bb);
    }
#undef DECIDE
    int gy = ty * 8 + yl, gx = tx * 8 + xl;
    g_s1[((b * 8 + o0) * 64 + gy) * 64 + gx] = h0;
    g_s1[((b * 8 + o1) * 64 + gy) * 64 + gx] = h1;
}

// ============================================================
// K3a: psp2 = psp(s1, tau=2) -> g_pspX [bc8][t][yx4096]
// ============================================================
__global__ void k_psp2()
{
    __shared__ u64 E[64], O[64];
    build_tables(d_kB, E, O);
    __syncthreads();

    int idx = blockIdx.x * 256 + threadIdx.x;   // 262144 = [b*8+c][y*64+x]
    u64 bits = g_s1[idx];
    u64 acc2[32];
#pragma unroll
    for (int j = 0; j < 32; j++) acc2[j] = 0ull;
    psp_fold(bits, E, O, acc2);

    int bc = idx >> 12, yx = idx & 4095;
    const float* a = (const float*)acc2;
#pragma unroll
    for (int t = 0; t < 64; t++)
        g_pspX[((size_t)bc * 64 + t) * 4096 + yx] = a[t];
}

// ============================================================
// K3b: layer2 deconv dot — f32 chain + band, f64 fallback (decision == f64)
// ============================================================
__global__ void k_layer2(const float* __restrict__ w2g)
{
    __shared__ float w[64], wabs[64], r2s[32];
    __shared__ double wd[64];
    if (threadIdx.x < 64) {
        float wv = w2g[threadIdx.x];
        w[threadIdx.x] = wv; wabs[threadIdx.x] = fabsf(wv); wd[threadIdx.x] = (double)wv;
    }
    if (threadIdx.x < 32) r2s[threadIdx.x] = d_r2[threadIdx.x];
    __syncthreads();

    int tid0 = blockIdx.x * 128 + threadIdx.x;  // 32768 pixels
    int b = tid0 >> 12, yx = tid0 & 4095;
    int y = yx >> 6, x = yx & 63;

    u64 h[8];
#pragma unroll
    for (int n = 0; n < 8; n++) h[n] = 0ull;

#pragma unroll 1
    for (int t = 0; t < 64; t++) {
        float p2[8];
#pragma unroll
        for (int c = 0; c < 8; c++)
            p2[c] = __ldg(&g_pspX[((size_t)(b * 8 + c) * 64 + t) * 4096 + yx]);
#pragma unroll
        for (int n = 0; n < 8; n++) {
            const int o = n >> 2, ij = n & 3;
            float z = 0.f, za = 0.f;
#pragma unroll
            for (int c = 0; c < 8; c++) {
                const int wi = (c * 2 + o) * 4 + ij;
                z  = __fmaf_rn(p2[c], w[wi], z);
                za = __fmaf_rn(fabsf(p2[c]), wabs[wi], za);
            }
            float rf = refr(h[n], r2s, t);
            double v = (double)z + (double)rf - 50.0;
            double B = (double)(za * 1.5e-6f);      // > gamma_8 = 8*2^-24, 3x margin
            bool s;
            if (v > B) s = true;
            else if (v < -B) s = false;
            else {
                double zd = 0.0;
#pragma unroll
                for (int c = 0; c < 8; c++)
                    zd = fma((double)p2[c], wd[(c * 2 + o) * 4 + ij], zd);
                s = (zd + (double)rf >= 50.0);
            }
            if (s) h[n] |= (1ull << t);
        }
    }
#pragma unroll
    for (int n = 0; n < 8; n++) {
        int o = n >> 2, i = (n >> 1) & 1, j = n & 1;
        g_s2[((b * 2 + o) * 128 + (2 * y + i)) * 128 + (2 * x + j)] = h[n];
    }
}

// ============================================================
// K4a: psp3 = psp(s2, tau=4) -> g_pspX [bc2][t][yx16384]
// ============================================================
__global__ void k_psp3()
{
    __shared__ u64 E[64], O[64];
    build_tables(d_kC, E, O);
    __syncthreads();

    int idx = blockIdx.x * 256 + threadIdx.x;   // 262144 = [b*2+o][yx16384]
    u64 bits = g_s2[idx];
    u64 acc2[32];
#pragma unroll
    for (int j = 0; j < 32; j++) acc2[j] = 0ull;
    psp_fold(bits, E, O, acc2);

    int bc = idx >> 14, yx = idx & 16383;
    const float* a = (const float*)acc2;
#pragma unroll
    for (int t = 0; t < 64; t++)
        g_pspX[((size_t)bc * 64 + t) * 16384 + yx] = a[t];
}

// ============================================================
// K4b: layer3 conv3x3 — f32 chain + band, f64 fallback; direct LDG (no smem tile,
//      no per-t barriers) + f32 bilinear skip + exact LIF
// ============================================================
__global__ void __launch_bounds__(256) k_layer3(const float* __restrict__ w3g,
                                                float* __restrict__ out)
{
    __shared__ float w[36], wabs[36], r3s[32];
    __shared__ double wd[36];
    if (threadIdx.x < 36) {
        float wv = w3g[threadIdx.x];
        w[threadIdx.x] = wv; wabs[threadIdx.x] = fabsf(wv); wd[threadIdx.x] = (double)wv;
    }
    if (threadIdx.x < 32) r3s[threadIdx.x] = d_r3[threadIdx.x];
    __syncthreads();

    int tid0 = blockIdx.x * 256 + threadIdx.x;  // 131072 threads
    int b = tid0 >> 14, yx = tid0 & 16383;
    int Y = yx >> 7, X = yx & 127;

    // neighbor offsets + validity (shared x values for both output channels)
    size_t nb[18];
    bool val[18];
#pragma unroll
    for (int c = 0; c < 2; c++)
#pragma unroll
        for (int ky = 0; ky < 3; ky++)
#pragma unroll
            for (int kx = 0; kx < 3; kx++) {
                int j = c * 9 + ky * 3 + kx;
                int gy = Y + ky - 1, gx = X + kx - 1;
                val[j] = ((unsigned)gy < 128u) && ((unsigned)gx < 128u);
                nb[j] = (size_t)(b * 2 + c) * 64 * 16384 + (size_t)(val[j] ? gy * 128 + gx : 0);
            }

    bool eY = (Y == 0) || (Y == 127);
    bool eX = (X == 0) || (X == 127);
    int y0 = (Y == 0) ? 0 : ((Y - 1) >> 1);
    int y1 = (y0 + 1 > 63) ? 63 : y0 + 1;
    int x0 = (X == 0) ? 0 : ((X - 1) >> 1);
    int x1 = (x0 + 1 > 63) ? 63 : x0 + 1;
    float wy1 = (Y & 1) ? 0.25f : 0.75f, wy0 = 1.f - wy1;
    float wx1 = (X & 1) ? 0.25f : 0.75f, wx0 = 1.f - wx1;

    const float* pr[2][4];
#pragma unroll
    for (int c = 0; c < 2; c++) {
        const float* base = &g_psp1[(size_t)(b * 2 + c) * 64 * 64 * 64];
        pr[c][0] = base + ((size_t)y0 * 64 + x0) * 64;
        pr[c][1] = base + ((size_t)y1 * 64 + x0) * 64;
        pr[c][2] = base + ((size_t)y0 * 64 + x1) * 64;
        pr[c][3] = base + ((size_t)y1 * 64 + x1) * 64;
    }

    u64 h[2] = {0ull, 0ull};

#pragma unroll 1
    for (int t = 0; t < 64; t++) {
        float xv[18];
        size_t toff = (size_t)t * 16384;
#pragma unroll
        for (int j = 0; j < 18; j++)
            xv[j] = val[j] ? __ldg(&g_pspX[nb[j] + toff]) : 0.f;

        float a0 = 0.f, a1 = 0.f, za0 = 0.f, za1 = 0.f;
#pragma unroll
        for (int j = 0; j < 18; j++) {
            float ax = fabsf(xv[j]);
            a0  = __fmaf_rn(w[j], xv[j], a0);
            za0 = __fmaf_rn(wabs[j], ax, za0);
            a1  = __fmaf_rn(w[18 + j], xv[j], a1);
            za1 = __fmaf_rn(wabs[18 + j], ax, za1);
        }

#pragma unroll
        for (int o = 0; o < 2; o++) {
            float p00 = pr[o][0][t], p10 = pr[o][1][t];
            float p01 = pr[o][2][t], p11 = pr[o][3][t];
            float A = eY ? p00 : __fmaf_rn(wy1, p10, __fmul_rn(wy0, p00));
            float B2 = eY ? p01 : __fmaf_rn(wy1, p11, __fmul_rn(wy0, p01));
            float skip = eX ? A : __fmaf_rn(wx1, B2, __fmul_rn(wx0, A));
            float rf = refr(h[o], r3s, t);
            double v = (double)(o ? a1 : a0) + (double)skip + (double)rf - 100.0;
            double B = (double)((o ? za1 : za0) * 3e-6f);  // > gamma_18, ~3x margin
            bool s;
            if (v > B) s = true;
            else if (v < -B) s = false;
            else {
                double ad = 0.0;
#pragma unroll
                for (int j = 0; j < 18; j++)
                    ad = fma(wd[o * 18 + j], (double)xv[j], ad);
                s = (ad + (double)skip + (double)rf >= 100.0);
            }
            if (s) h[o] |= (1ull << t);
        }
    }

#pragma unroll
    for (int o = 0; o < 2; o++) {
        float4* dst = (float4*)(out + ((size_t)((b * 2 + o) * 128 + Y) * 128 + X) * 64);
        u64 m = h[o];
#pragma unroll
        for (int k = 0; k < 16; k++) {
            float4 v;
            v.x = (float)((unsigned)((m >> (4 * k + 0)) & 1ull));
            v.y = (float)((unsigned)((m >> (4 * k + 1)) & 1ull));
            v.z = (float)((unsigned)((m >> (4 * k + 2)) & 1ull));
            v.w = (float)((unsigned)((m >> (4 * k + 3)) & 1ull));
            dst[k] = v;
        }
    }
}

extern "C" void kernel_launch(void* const* d_in, const int* in_sizes, int n_in,
                              void* d_out, int out_size)
{
    const float* in = (const float*)d_in[0];
    const float* w1 = (const float*)d_in[1];
    const float* w2 = (const float*)d_in[2];
    const float* w3 = (const float*)d_in[3];
    float* out = (float*)d_out;

    cudaFuncSetAttribute(k_layer1, cudaFuncAttributeMaxDynamicSharedMemorySize,
                         2 * 144 * TPAD * 4);

    k_init<<<1, 64>>>();
    k_psp1<<<256, 256>>>(in);
    dim3 g1(8, 8, 8);
    k_layer1<<<g1, 256, 2 * 144 * TPAD * 4>>>(w1);
    k_psp2<<<1024, 256>>>();
    k_layer2<<<256, 128>>>(w2);
    k_psp3<<<1024, 256>>>();
    k_layer3<<<512, 256>>>(w3, out);
}

// round 12
// speedup vs baseline: 4.7981x; 1.3590x over previous
#include <cuda_runtime.h>
#include <cstdint>

typedef unsigned long long u64;

// ---- exact f32 tap tables ----
__device__ float d_kA[64], d_kB[64], d_kC[64];   // psp taps tau = 1, 2, 4
__device__ float d_r1[32], d_r2[32], d_r3[32];   // refractory taps per layer

// ---- scratch (device globals; allocations forbidden) ----
__device__ __align__(256) float g_psp1[8 * 2 * 64 * 64 * 64];      // [b][c][y][x][t]
__device__ __align__(256) u64 g_s1[8 * 8 * 64 * 64];               // layer1 spike bits
__device__ __align__(256) u64 g_s2[8 * 2 * 128 * 128];             // layer2 spike bits
__device__ __align__(256) float g_pspX[16ull * 64 * 16384];        // psp2 [bc8][t][yx4096] then psp3 [bc2][t][yx16384]

// ============================================================
__global__ void k_init()
{
    int d = threadIdx.x;   // 0..63
    float df = (float)d;
    float aA = df;
    float aB = __fmul_rn(df, 0.5f);
    float aC = __fmul_rn(df, 0.25f);
    float kA = __fmul_rn(aA, expf(__fsub_rn(1.0f, aA)));
    float kB = __fmul_rn(aB, expf(__fsub_rn(1.0f, aB)));
    float kC = __fmul_rn(aC, expf(__fsub_rn(1.0f, aC)));
    d_kA[d] = kA; d_kB[d] = kB; d_kC[d] = kC;
    if (d < 32) {
        d_r1[d] = __fmul_rn(-60.0f, kA);
        d_r2[d] = __fmul_rn(-100.0f, kB);
        d_r3[d] = __fmul_rn(-200.0f, kC);
    }
}

// Refractory: fold over spikes t_x in [t-32, t-1], oldest first, of r[t-1-t_x]. (bit-exact)
__device__ __forceinline__ float refr(u64 h, const float* __restrict__ r, int t)
{
    if (t == 0) return 0.f;
    u64 hi = (1ull << t) - 1ull;
    u64 lo = (t >= 33) ? ((1ull << (t - 32)) - 1ull) : 0ull;
    u64 m = h & hi & ~lo;
    float acc = 0.f;
    while (m) {
        int i = __ffsll((long long)m) - 1;
        acc = __fadd_rn(acc, r[t - 1 - i]);
        m &= m - 1;
    }
    return acc;
}

// ============================================================
// Shifted-tap tables for vectorized psp fold (bit-identical to serial tapsum).
// ============================================================
__device__ __forceinline__ void build_tables(const float* __restrict__ kk, u64* E, u64* O)
{
    for (int m = threadIdx.x; m < 64; m += blockDim.x) {
        float e0 = (2 * m - 64 >= 0) ? kk[2 * m - 64] : 0.f;
        float e1 = (2 * m - 63 >= 0) ? kk[2 * m - 63] : 0.f;
        float o1 = (2 * m - 62 >= 0) ? kk[2 * m - 62] : 0.f;
        E[m] = ((u64)__float_as_uint(e1) << 32) | (u64)__float_as_uint(e0);
        O[m] = ((u64)__float_as_uint(o1) << 32) | (u64)__float_as_uint(e1);
    }
}

__device__ __forceinline__ void psp_fold(u64 bits, const u64* __restrict__ E,
                                         const u64* __restrict__ O, u64* acc2)
{
    while (bits) {
        int i = __ffsll((long long)bits) - 1;
        bits &= bits - 1;
        const u64* base = (i & 1) ? (O + (31 - ((i - 1) >> 1))) : (E + (32 - (i >> 1)));
#pragma unroll
        for (int j = 0; j < 32; j++)
            asm("add.rn.f32x2 %0, %0, %1;" : "+l"(acc2[j]) : "l"(base[j]));
    }
}

// ============================================================
// K1: psp1 (tau=1) via shifted-tap vector fold; writes dense [b][c][y][x][t]
// ============================================================
__global__ void k_psp1(const float* __restrict__ in)
{
    __shared__ u64 E[64], O[64];
    build_tables(d_kA, E, O);
    __syncthreads();

    int r = blockIdx.x * 256 + threadIdx.x;     // 65536 rows
    const float4* src = (const float4*)(in + (size_t)r * 64);
    u64 bits = 0ull;
#pragma unroll
    for (int i = 0; i < 16; i++) {
        float4 x = src[i];
        bits |= ((u64)(x.x > 0.5f)) << (4 * i + 0);
        bits |= ((u64)(x.y > 0.5f)) << (4 * i + 1);
        bits |= ((u64)(x.z > 0.5f)) << (4 * i + 2);
        bits |= ((u64)(x.w > 0.5f)) << (4 * i + 3);
    }
    u64 acc2[32];
#pragma unroll
    for (int j = 0; j < 32; j++) acc2[j] = 0ull;
    psp_fold(bits, E, O, acc2);

    const float* a = (const float*)acc2;
    float4* dst = (float4*)(g_psp1 + (size_t)r * 64);
#pragma unroll
    for (int q = 0; q < 16; q++)
        dst[q] = make_float4(a[4 * q], a[4 * q + 1], a[4 * q + 2], a[4 * q + 3]);
}

// ============================================================
// K2: layer1 conv5x5 — f32x2 fast path + ALL-f32 band test; f64 fallback in band
// ============================================================
#define TPAD 68
__global__ void __launch_bounds__(256) k_layer1(const float* __restrict__ w1)
{
    __shared__ float r1s[32];
    extern __shared__ float sm[];    // [2][12][12][TPAD]
    int tid = threadIdx.x;
    if (tid < 32) r1s[tid] = d_r1[tid];

    int b = blockIdx.z, ty = blockIdx.y, tx = blockIdx.x;
    int gy0 = ty * 8 - 2, gx0 = tx * 8 - 2;
    for (int rr = tid; rr < 288 * 16; rr += 256) {
        int chunk = rr & 15, row = rr >> 4;
        int c = row / 144, rem = row - c * 144;
        int ly = rem / 12, lx = rem - ly * 12;
        int gy = gy0 + ly, gx = gx0 + lx;
        float4 v = make_float4(0.f, 0.f, 0.f, 0.f);
        if ((unsigned)gy < 64u && (unsigned)gx < 64u)
            v = *(const float4*)&g_psp1[(((size_t)((b * 2 + c) * 64 + gy) * 64 + gx) << 6) + chunk * 4];
        float* d = &sm[((c * 12 + ly) * 12 + lx) * TPAD + chunk * 4];
        d[0] = v.x; d[1] = v.y; d[2] = v.z; d[3] = v.w;
    }
    __syncthreads();

    int og = tid & 3, pix = tid >> 2;
    int yl = pix >> 3, xl = pix & 7;
    int o0 = og * 2, o1 = og * 2 + 1;

    float wa[50], wb[50];
    float Wa = 0.f, Wb = 0.f;
#pragma unroll
    for (int k = 0; k < 50; k++) {
        wa[k] = __ldg(&w1[o0 * 50 + k]);
        wb[k] = __ldg(&w1[o1 * 50 + k]);
        Wa += fabsf(wa[k]);
        Wb += fabsf(wb[k]);
    }
    // |f32 chain - exact| <= gamma_50 * Sum|w| * max(psp1=2.51), with margin
    float Ba = Wa * 8.2e-6f;
    float Bb = Wb * 8.2e-6f;

    const float* basep = &sm[(yl * 12 + xl) * TPAD];
    u64 h0 = 0ull, h1 = 0ull;

#define DECIDE(h, uval, tt, oo, BBf) do {                                         \
    float rf_ = refr(h, r1s, tt);                                                 \
    float m_  = __fadd_rn(uval, rf_);                                             \
    float dd_ = __fadd_rn(m_, -30.f);                                             \
    float bt_ = __fmaf_rn(1.2e-7f, __fadd_rn(fabsf(m_), fabsf(dd_)), BBf);        \
    bool s_;                                                                      \
    if (dd_ > bt_) s_ = true;                                                     \
    else if (dd_ < -bt_) s_ = false;                                              \
    else {                                                                        \
        double a_ = 0.0;                                                          \
        _Pragma("unroll 1")                                                       \
        for (int kk_ = 0; kk_ < 50; kk_++) {                                      \
            int c_ = kk_ / 25, rm_ = kk_ % 25, ky_ = rm_ / 5, kx_ = rm_ % 5;      \
            a_ = fma((double)__ldg(&w1[(oo) * 50 + kk_]),                         \
                     (double)basep[(c_ * 144 + ky_ * 12 + kx_) * TPAD + (tt)], a_);\
        }                                                                         \
        s_ = (a_ + (double)rf_ >= 30.0);                                          \
    }                                                                             \
    if (s_) h |= (1ull << (tt));                                                  \
} while (0)

#pragma unroll 1
    for (int tp = 0; tp < 32; tp++) {
        u64 acc0 = 0ull, acc1 = 0ull;
        const u64* xp = (const u64*)(basep + 2 * tp);
#pragma unroll
        for (int ky = 0; ky < 5; ky++)
#pragma unroll
            for (int kx = 0; kx < 5; kx++)
#pragma unroll
                for (int c = 0; c < 2; c++) {
                    const int k = c * 25 + ky * 5 + kx;
                    u64 x2 = xp[(c * 144 + ky * 12 + kx) * (TPAD / 2)];
                    u64 wv;
                    asm("mov.b64 %0, {%1, %1};" : "=l"(wv) : "f"(wa[k]));
                    asm("fma.rn.f32x2 %0, %1, %2, %0;" : "+l"(acc0) : "l"(wv), "l"(x2));
                    asm("mov.b64 %0, {%1, %1};" : "=l"(wv) : "f"(wb[k]));
                    asm("fma.rn.f32x2 %0, %1, %2, %0;" : "+l"(acc1) : "l"(wv), "l"(x2));
                }
        float ua0, ua1, ub0, ub1;
        asm("mov.b64 {%0, %1}, %2;" : "=f"(ua0), "=f"(ua1) : "l"(acc0));
        asm("mov.b64 {%0, %1}, %2;" : "=f"(ub0), "=f"(ub1) : "l"(acc1));
        int t = 2 * tp;
        DECIDE(h0, ua0, t,     o0, Ba);
        DECIDE(h0, ua1, t + 1, o0, Ba);
        DECIDE(h1, ub0, t,     o1, Bb);
        DECIDE(h1, ub1, t + 1, o1, Bb);
    }
#undef DECIDE
    int gy = ty * 8 + yl, gx = tx * 8 + xl;
    g_s1[((b * 8 + o0) * 64 + gy) * 64 + gx] = h0;
    g_s1[((b * 8 + o1) * 64 + gy) * 64 + gx] = h1;
}

// ============================================================
// K3a: psp2 = psp(s1, tau=2) -> g_pspX [bc8][t][yx4096]
// ============================================================
__global__ void k_psp2()
{
    __shared__ u64 E[64], O[64];
    build_tables(d_kB, E, O);
    __syncthreads();

    int idx = blockIdx.x * 256 + threadIdx.x;   // 262144 = [b*8+c][y*64+x]
    u64 bits = g_s1[idx];
    u64 acc2[32];
#pragma unroll
    for (int j = 0; j < 32; j++) acc2[j] = 0ull;
    psp_fold(bits, E, O, acc2);

    int bc = idx >> 12, yx = idx & 4095;
    const float* a = (const float*)acc2;
#pragma unroll
    for (int t = 0; t < 64; t++)
        g_pspX[((size_t)bc * 64 + t) * 4096 + yx] = a[t];
}

// ============================================================
// K3b: layer2 deconv — 4x parallel (thread = (b, ij, yx), 2 neurons o=0/1);
// f32 chain + constant bound + all-f32 test; f64 fallback (decision == R9)
// ============================================================
__global__ void k_layer2(const float* __restrict__ w2g)
{
    __shared__ float w[64], r2s[32];
    __shared__ double wd[64];
    if (threadIdx.x < 64) {
        float wv = w2g[threadIdx.x];
        w[threadIdx.x] = wv; wd[threadIdx.x] = (double)wv;
    }
    if (threadIdx.x < 32) r2s[threadIdx.x] = d_r2[threadIdx.x];
    __syncthreads();

    int tid0 = blockIdx.x * 256 + threadIdx.x;  // 131072 = [b][ij][yx]
    int b = tid0 >> 14, ij = (tid0 >> 12) & 3, yx = tid0 & 4095;
    int y = yx >> 6, x = yx & 63;

    // constant chain bounds: |psp2| <= Sum taps(tau=2) < 5.4
    float W0 = 0.f, W1 = 0.f;
#pragma unroll
    for (int c = 0; c < 8; c++) {
        W0 += fabsf(w[(c * 2 + 0) * 4 + ij]);
        W1 += fabsf(w[(c * 2 + 1) * 4 + ij]);
    }
    float Bn[2] = { W0 * 4.0e-6f, W1 * 4.0e-6f };  // gamma_8 * 5.4 * 1.5 margin

    u64 h[2] = {0ull, 0ull};

#pragma unroll 1
    for (int t = 0; t < 64; t++) {
        float p2[8];
#pragma unroll
        for (int c = 0; c < 8; c++)
            p2[c] = __ldg(&g_pspX[((size_t)(b * 8 + c) * 64 + t) * 4096 + yx]);
#pragma unroll
        for (int o = 0; o < 2; o++) {
            float z = 0.f;
#pragma unroll
            for (int c = 0; c < 8; c++)
                z = __fmaf_rn(p2[c], w[(c * 2 + o) * 4 + ij], z);
            float rf = refr(h[o], r2s, t);
            float m  = __fadd_rn(z, rf);
            float dd = __fadd_rn(m, -50.f);
            float bt = __fmaf_rn(1.2e-7f, __fadd_rn(fabsf(m), fabsf(dd)), Bn[o]);
            bool s;
            if (dd > bt) s = true;
            else if (dd < -bt) s = false;
            else {
                double zd = 0.0;
#pragma unroll
                for (int c = 0; c < 8; c++)
                    zd = fma((double)p2[c], wd[(c * 2 + o) * 4 + ij], zd);
                s = (zd + (double)rf >= 50.0);
            }
            if (s) h[o] |= (1ull << t);
        }
    }
    int i = ij >> 1, j = ij & 1;
#pragma unroll
    for (int o = 0; o < 2; o++)
        g_s2[((b * 2 + o) * 128 + (2 * y + i)) * 128 + (2 * x + j)] = h[o];
}

// ============================================================
// K4a: psp3 = psp(s2, tau=4) -> g_pspX [bc2][t][yx16384]
// ============================================================
__global__ void k_psp3()
{
    __shared__ u64 E[64], O[64];
    build_tables(d_kC, E, O);
    __syncthreads();

    int idx = blockIdx.x * 256 + threadIdx.x;   // 262144 = [b*2+o][yx16384]
    u64 bits = g_s2[idx];
    u64 acc2[32];
#pragma unroll
    for (int j = 0; j < 32; j++) acc2[j] = 0ull;
    psp_fold(bits, E, O, acc2);

    int bc = idx >> 14, yx = idx & 16383;
    const float* a = (const float*)acc2;
#pragma unroll
    for (int t = 0; t < 64; t++)
        g_pspX[((size_t)bc * 64 + t) * 16384 + yx] = a[t];
}

// ============================================================
// K4b: layer3 conv3x3 — f32 chain + constant bound + all-f32 test; f64 fallback;
//      direct LDG + f32 bilinear skip + exact LIF
// ============================================================
__global__ void __launch_bounds__(256) k_layer3(const float* __restrict__ w3g,
                                                float* __restrict__ out)
{
    __shared__ float w[36], r3s[32];
    __shared__ double wd[36];
    if (threadIdx.x < 36) {
        float wv = w3g[threadIdx.x];
        w[threadIdx.x] = wv; wd[threadIdx.x] = (double)wv;
    }
    if (threadIdx.x < 32) r3s[threadIdx.x] = d_r3[threadIdx.x];
    __syncthreads();

    int tid0 = blockIdx.x * 256 + threadIdx.x;  // 131072 threads
    int b = tid0 >> 14, yx = tid0 & 16383;
    int Y = yx >> 7, X = yx & 127;

    // constant chain bounds: |psp3| <= Sum taps(tau=4) < 11.0
    float W30 = 0.f, W31 = 0.f;
#pragma unroll
    for (int j = 0; j < 18; j++) { W30 += fabsf(w[j]); W31 += fabsf(w[18 + j]); }
    float Bn[2] = { W30 * 1.8e-5f, W31 * 1.8e-5f };  // gamma_18 * 11 * 1.5 margin

    size_t nb[18];
    bool val[18];
#pragma unroll
    for (int c = 0; c < 2; c++)
#pragma unroll
        for (int ky = 0; ky < 3; ky++)
#pragma unroll
            for (int kx = 0; kx < 3; kx++) {
                int j = c * 9 + ky * 3 + kx;
                int gy = Y + ky - 1, gx = X + kx - 1;
                val[j] = ((unsigned)gy < 128u) && ((unsigned)gx < 128u);
                nb[j] = (size_t)(b * 2 + c) * 64 * 16384 + (size_t)(val[j] ? gy * 128 + gx : 0);
            }

    bool eY = (Y == 0) || (Y == 127);
    bool eX = (X == 0) || (X == 127);
    int y0 = (Y == 0) ? 0 : ((Y - 1) >> 1);
    int y1 = (y0 + 1 > 63) ? 63 : y0 + 1;
    int x0 = (X == 0) ? 0 : ((X - 1) >> 1);
    int x1 = (x0 + 1 > 63) ? 63 : x0 + 1;
    float wy1 = (Y & 1) ? 0.25f : 0.75f, wy0 = 1.f - wy1;
    float wx1 = (X & 1) ? 0.25f : 0.75f, wx0 = 1.f - wx1;

    const float* pr[2][4];
#pragma unroll
    for (int c = 0; c < 2; c++) {
        const float* base = &g_psp1[(size_t)(b * 2 + c) * 64 * 64 * 64];
        pr[c][0] = base + ((size_t)y0 * 64 + x0) * 64;
        pr[c][1] = base + ((size_t)y1 * 64 + x0) * 64;
        pr[c][2] = base + ((size_t)y0 * 64 + x1) * 64;
        pr[c][3] = base + ((size_t)y1 * 64 + x1) * 64;
    }

    u64 h[2] = {0ull, 0ull};

#pragma unroll 1
    for (int t = 0; t < 64; t++) {
        float xv[18];
        size_t toff = (size_t)t * 16384;
#pragma unroll
        for (int j = 0; j < 18; j++)
            xv[j] = val[j] ? __ldg(&g_pspX[nb[j] + toff]) : 0.f;

        float a0 = 0.f, a1 = 0.f;
#pragma unroll
        for (int j = 0; j < 18; j++) {
            a0 = __fmaf_rn(w[j], xv[j], a0);
            a1 = __fmaf_rn(w[18 + j], xv[j], a1);
        }

#pragma unroll
        for (int o = 0; o < 2; o++) {
            float p00 = pr[o][0][t], p10 = pr[o][1][t];
            float p01 = pr[o][2][t], p11 = pr[o][3][t];
            float A  = eY ? p00 : __fmaf_rn(wy1, p10, __fmul_rn(wy0, p00));
            float B2 = eY ? p01 : __fmaf_rn(wy1, p11, __fmul_rn(wy0, p01));
            float skip = eX ? A : __fmaf_rn(wx1, B2, __fmul_rn(wx0, A));
            float rf = refr(h[o], r3s, t);
            float m1 = __fadd_rn((o ? a1 : a0), skip);
            float m  = __fadd_rn(m1, rf);
            float dd = __fadd_rn(m, -100.f);
            float bt = __fmaf_rn(1.2e-7f,
                        __fadd_rn(fabsf(m1), __fadd_rn(fabsf(m), fabsf(dd))), Bn[o]);
            bool s;
            if (dd > bt) s = true;
            else if (dd < -bt) s = false;
            else {
                double ad = 0.0;
#pragma unroll
                for (int j = 0; j < 18; j++)
                    ad = fma(wd[o * 18 + j], (double)xv[j], ad);
                s = (ad + (double)skip + (double)rf >= 100.0);
            }
            if (s) h[o] |= (1ull << t);
        }
    }

#pragma unroll
    for (int o = 0; o < 2; o++) {
        float4* dst = (float4*)(out + ((size_t)((b * 2 + o) * 128 + Y) * 128 + X) * 64);
        u64 m = h[o];
#pragma unroll
        for (int k = 0; k < 16; k++) {
            float4 v;
            v.x = (float)((unsigned)((m >> (4 * k + 0)) & 1ull));
            v.y = (float)((unsigned)((m >> (4 * k + 1)) & 1ull));
            v.z = (float)((unsigned)((m >> (4 * k + 2)) & 1ull));
            v.w = (float)((unsigned)((m >> (4 * k + 3)) & 1ull));
            dst[k] = v;
        }
    }
}

extern "C" void kernel_launch(void* const* d_in, const int* in_sizes, int n_in,
                              void* d_out, int out_size)
{
    const float* in = (const float*)d_in[0];
    const float* w1 = (const float*)d_in[1];
    const float* w2 = (const float*)d_in[2];
    const float* w3 = (const float*)d_in[3];
    float* out = (float*)d_out;

    cudaFuncSetAttribute(k_layer1, cudaFuncAttributeMaxDynamicSharedMemorySize,
                         2 * 144 * TPAD * 4);

    k_init<<<1, 64>>>();
    k_psp1<<<256, 256>>>(in);
    dim3 g1(8, 8, 8);
    k_layer1<<<g1, 256, 2 * 144 * TPAD * 4>>>(w1);
    k_psp2<<<1024, 256>>>();
    k_layer2<<<512, 256>>>(w2);
    k_psp3<<<1024, 256>>>();
    k_layer3<<<512, 256>>>(w3, out);
}

// round 14
// speedup vs baseline: 6.9433x; 1.4471x over previous
#include <cuda_runtime.h>
#include <cstdint>

typedef unsigned long long u64;

// ---- recurrence constants ----
#define A1f 0.36787944117144233f
#define C1f 2.7182818284590452f
#define A2f 0.60653065971263342f
#define C2f 1.3591409142295226f
#define A4f 0.77880078307140488f
#define C4f 0.67957045711476128f
#define CC1f (-163.09690970754271f)   // -60 * e/1
#define CC2f (-135.91409142295226f)   // -100 * e/2
#define CC3f (-135.91409142295226f)   // -200 * e/4
#define CT3f (-4.5593365e-2f)         // CC3 * e^-8  (32-step tail factor, tau=4)

// ---- exact f32 tap tables (for exact fallback folds) ----
__device__ float d_kA[64], d_kB[64], d_kC[64];
__device__ float d_r1[32], d_r2[32], d_r3[32];

// ---- scratch ----
__device__ __align__(256) float g_psp1[8 * 2 * 64 * 64 * 64];   // [b][c][y][x][t]
__device__ __align__(256) u64 g_inbits[8 * 2 * 64 * 64];
__device__ __align__(256) u64 g_s1[8 * 8 * 64 * 64];
__device__ __align__(256) u64 g_s2[8 * 2 * 128 * 128];
__device__ __align__(256) float g_pspX[16ull * 64 * 16384];     // psp2 [bc8][t][yx4096] / psp3 [bc2][t][yx16384]

// ============================================================
__global__ void k_init()
{
    int d = threadIdx.x;
    float df = (float)d;
    float aA = df;
    float aB = __fmul_rn(df, 0.5f);
    float aC = __fmul_rn(df, 0.25f);
    float kA = __fmul_rn(aA, expf(__fsub_rn(1.0f, aA)));
    float kB = __fmul_rn(aB, expf(__fsub_rn(1.0f, aB)));
    float kC = __fmul_rn(aC, expf(__fsub_rn(1.0f, aC)));
    d_kA[d] = kA; d_kB[d] = kB; d_kC[d] = kC;
    if (d < 32) {
        d_r1[d] = __fmul_rn(-60.0f, kA);
        d_r2[d] = __fmul_rn(-100.0f, kB);
        d_r3[d] = __fmul_rn(-200.0f, kC);
    }
}

// exact psp fold (fallback only): oldest spike first, f32 adds — R9-bit-exact
__device__ __forceinline__ float tapsum(u64 bits, const float* __restrict__ k, int t)
{
    u64 m = bits & ((t >= 63) ? ~0ull : ((1ull << (t + 1)) - 1ull));
    float acc = 0.f;
    while (m) {
        int i = __ffsll((long long)m) - 1;
        acc = __fadd_rn(acc, k[t - i]);
        m &= m - 1;
    }
    return acc;
}

// exact refractory fold (fallback only): window [t-32, t-1], oldest first — R9-bit-exact
__device__ __forceinline__ float refr(u64 h, const float* __restrict__ r, int t)
{
    if (t == 0) return 0.f;
    u64 hi = (1ull << t) - 1ull;
    u64 lo = (t >= 33) ? ((1ull << (t - 32)) - 1ull) : 0ull;
    u64 m = h & hi & ~lo;
    float acc = 0.f;
    while (m) {
        int i = __ffsll((long long)m) - 1;
        acc = __fadd_rn(acc, r[t - 1 - i]);
        m &= m - 1;
    }
    return acc;
}

// ============================================================
// K1: psp1 via O(1)/step recurrence (band-guarded downstream); writes inbits too
// psp form (contribution k(t-t_x), k(0)=0 via emit-before-update) — verified exact form
// ============================================================
__global__ void k_psp1(const float* __restrict__ in)
{
    int r = blockIdx.x * 256 + threadIdx.x;     // 65536 rows
    const float4* src = (const float4*)(in + (size_t)r * 64);
    u64 bits = 0ull;
#pragma unroll
    for (int i = 0; i < 16; i++) {
        float4 x = src[i];
        bits |= ((u64)(x.x > 0.5f)) << (4 * i + 0);
        bits |= ((u64)(x.y > 0.5f)) << (4 * i + 1);
        bits |= ((u64)(x.z > 0.5f)) << (4 * i + 2);
        bits |= ((u64)(x.w > 0.5f)) << (4 * i + 3);
    }
    g_inbits[r] = bits;

    float P = 0.f, Q = 0.f;
    float buf[64];
#pragma unroll
    for (int t = 0; t < 64; t++) {
        buf[t] = __fmul_rn(C1f, Q);
        float s = (float)((unsigned)((bits >> t) & 1ull));
        float tq = __fadd_rn(__fadd_rn(Q, P), s);
        Q = __fmul_rn(A1f, tq);
        P = __fmul_rn(A1f, __fadd_rn(P, s));
    }
    float4* dst = (float4*)(g_psp1 + (size_t)r * 64);
#pragma unroll
    for (int q = 0; q < 16; q++)
        dst[q] = make_float4(buf[4 * q], buf[4 * q + 1], buf[4 * q + 2], buf[4 * q + 3]);
}

// ============================================================
// K2: layer1 conv5x5 — f32x2 chain + CORRECTED refr recurrence + band; exact fallback
// refr form: at decision R = CC*S; after decision: S <- a(S+T); T <- a*T + s
// (spike's first contribution is k(0)=0, d-th is k(d-1) — matches r[t-1-t_x])
// ============================================================
#define TPAD 68
__global__ void __launch_bounds__(256) k_layer1(const float* __restrict__ w1)
{
    __shared__ float r1s[32];
    __shared__ u64 ibt[288];         // inbits tile [2][12][12]
    extern __shared__ float sm[];    // psp1 tile [2][12][12][TPAD]
    int tid = threadIdx.x;
    if (tid < 32) r1s[tid] = d_r1[tid];

    int b = blockIdx.z, ty = blockIdx.y, tx = blockIdx.x;
    int gy0 = ty * 8 - 2, gx0 = tx * 8 - 2;
    for (int i = tid; i < 288; i += 256) {
        int c = i / 144, rem = i - c * 144;
        int ly = rem / 12, lx = rem - ly * 12;
        int gy = gy0 + ly, gx = gx0 + lx;
        ibt[i] = ((unsigned)gy < 64u && (unsigned)gx < 64u)
                     ? g_inbits[(b * 2 + c) * 4096 + gy * 64 + gx] : 0ull;
    }
    for (int rr = tid; rr < 288 * 16; rr += 256) {
        int chunk = rr & 15, row = rr >> 4;
        int c = row / 144, rem = row - c * 144;
        int ly = rem / 12, lx = rem - ly * 12;
        int gy = gy0 + ly, gx = gx0 + lx;
        float4 v = make_float4(0.f, 0.f, 0.f, 0.f);
        if ((unsigned)gy < 64u && (unsigned)gx < 64u)
            v = *(const float4*)&g_psp1[(((size_t)((b * 2 + c) * 64 + gy) * 64 + gx) << 6) + chunk * 4];
        float* d = &sm[((c * 12 + ly) * 12 + lx) * TPAD + chunk * 4];
        d[0] = v.x; d[1] = v.y; d[2] = v.z; d[3] = v.w;
    }
    __syncthreads();

    int og = tid & 3, pix = tid >> 2;
    int yl = pix >> 3, xl = pix & 7;
    int o0 = og * 2, o1 = og * 2 + 1;

    float wa[50], wb[50];
    float Wa = 0.f, Wb = 0.f;
#pragma unroll
    for (int k = 0; k < 50; k++) {
        wa[k] = __ldg(&w1[o0 * 50 + k]);
        wb[k] = __ldg(&w1[o1 * 50 + k]);
        Wa += fabsf(wa[k]);
        Wb += fabsf(wb[k]);
    }
    float Ba = __fmaf_rn(Wa, 1.9e-5f, 0.004f);
    float Bb = __fmaf_rn(Wb, 1.9e-5f, 0.004f);

    const float* basep = &sm[(yl * 12 + xl) * TPAD];
    u64 h0 = 0ull, h1 = 0ull;
    float P0 = 0.f, Q0 = 0.f, P1 = 0.f, Q1 = 0.f;   // T, S refr states

#define DECIDE1(h, uval, tt, oo, BBf, PP, QQ) do {                                \
    float R_ = __fmul_rn(CC1f, QQ);                                               \
    float m_  = __fadd_rn(uval, R_);                                              \
    float dd_ = __fadd_rn(m_, -30.f);                                             \
    float bt_ = __fmaf_rn(1.2e-7f, __fadd_rn(fabsf(m_), fabsf(dd_)), BBf);        \
    bool s_;                                                                      \
    if (dd_ > bt_) s_ = true;                                                     \
    else if (dd_ < -bt_) s_ = false;                                              \
    else {                                                                        \
        double a_ = 0.0;                                                          \
        _Pragma("unroll 1")                                                       \
        for (int kk_ = 0; kk_ < 50; kk_++) {                                      \
            int c_ = kk_ / 25, rm_ = kk_ % 25, ky_ = rm_ / 5, kx_ = rm_ % 5;      \
            int pos_ = c_ * 144 + (yl + ky_) * 12 + (xl + kx_);                   \
            a_ = fma((double)__ldg(&w1[(oo) * 50 + kk_]),                         \
                     (double)tapsum(ibt[pos_], d_kA, tt), a_);                    \
        }                                                                         \
        s_ = (a_ + (double)refr(h, r1s, tt) >= 30.0);                             \
    }                                                                             \
    float sf_ = s_ ? 1.f : 0.f;                                                   \
    QQ = __fmul_rn(A1f, __fadd_rn(QQ, PP));                                       \
    PP = __fmaf_rn(A1f, PP, sf_);                                                 \
    if (s_) h |= (1ull << (tt));                                                  \
} while (0)

#pragma unroll 1
    for (int tp = 0; tp < 32; tp++) {
        u64 acc0 = 0ull, acc1 = 0ull;
        const u64* xp = (const u64*)(basep + 2 * tp);
#pragma unroll
        for (int ky = 0; ky < 5; ky++)
#pragma unroll
            for (int kx = 0; kx < 5; kx++)
#pragma unroll
                for (int c = 0; c < 2; c++) {
                    const int k = c * 25 + ky * 5 + kx;
                    u64 x2 = xp[(c * 144 + ky * 12 + kx) * (TPAD / 2)];
                    u64 wv;
                    asm("mov.b64 %0, {%1, %1};" : "=l"(wv) : "f"(wa[k]));
                    asm("fma.rn.f32x2 %0, %1, %2, %0;" : "+l"(acc0) : "l"(wv), "l"(x2));
                    asm("mov.b64 %0, {%1, %1};" : "=l"(wv) : "f"(wb[k]));
                    asm("fma.rn.f32x2 %0, %1, %2, %0;" : "+l"(acc1) : "l"(wv), "l"(x2));
                }
        float ua0, ua1, ub0, ub1;
        asm("mov.b64 {%0, %1}, %2;" : "=f"(ua0), "=f"(ua1) : "l"(acc0));
        asm("mov.b64 {%0, %1}, %2;" : "=f"(ub0), "=f"(ub1) : "l"(acc1));
        int t = 2 * tp;
        DECIDE1(h0, ua0, t,     o0, Ba, P0, Q0);
        DECIDE1(h0, ua1, t + 1, o0, Ba, P0, Q0);
        DECIDE1(h1, ub0, t,     o1, Bb, P1, Q1);
        DECIDE1(h1, ub1, t + 1, o1, Bb, P1, Q1);
    }
#undef DECIDE1
    int gy = ty * 8 + yl, gx = tx * 8 + xl;
    g_s1[((b * 8 + o0) * 64 + gy) * 64 + gx] = h0;
    g_s1[((b * 8 + o1) * 64 + gy) * 64 + gx] = h1;
}

// ============================================================
// K3a: psp2 via recurrence -> g_pspX [bc8][t][yx4096] (coalesced stores)
// ============================================================
__global__ void k_psp2()
{
    int idx = blockIdx.x * 256 + threadIdx.x;   // 262144 = [b*8+c][yx]
    u64 bits = g_s1[idx];
    int bc = idx >> 12, yx = idx & 4095;
    float* base = g_pspX + (size_t)bc * 64 * 4096 + yx;
    float P = 0.f, Q = 0.f;
#pragma unroll
    for (int t = 0; t < 64; t++) {
        base[(size_t)t * 4096] = __fmul_rn(C2f, Q);
        float s = (float)((unsigned)((bits >> t) & 1ull));
        float tq = __fadd_rn(__fadd_rn(Q, P), s);
        Q = __fmul_rn(A2f, tq);
        P = __fmul_rn(A2f, __fadd_rn(P, s));
    }
}

// ============================================================
// K3b: layer2 deconv — f32 dot + CORRECTED refr recurrence + band; exact fallback
// ============================================================
__global__ void k_layer2(const float* __restrict__ w2g)
{
    __shared__ float w[64], r2s[32];
    if (threadIdx.x < 64) w[threadIdx.x] = w2g[threadIdx.x];
    if (threadIdx.x < 32) r2s[threadIdx.x] = d_r2[threadIdx.x];
    __syncthreads();

    int tid0 = blockIdx.x * 256 + threadIdx.x;  // 131072 = [b][ij][yx]
    int b = tid0 >> 14, ij = (tid0 >> 12) & 3, yx = tid0 & 4095;
    int y = yx >> 6, x = yx & 63;

    float W0 = 0.f, W1 = 0.f;
#pragma unroll
    for (int c = 0; c < 8; c++) {
        W0 += fabsf(w[(c * 2 + 0) * 4 + ij]);
        W1 += fabsf(w[(c * 2 + 1) * 4 + ij]);
    }
    float Bn[2] = { __fmaf_rn(W0, 3.4e-5f, 0.01f), __fmaf_rn(W1, 3.4e-5f, 0.01f) };

    u64 h[2] = {0ull, 0ull};
    float P[2] = {0.f, 0.f}, Q[2] = {0.f, 0.f};   // T, S

#pragma unroll 1
    for (int t = 0; t < 64; t++) {
        float p2[8];
#pragma unroll
        for (int c = 0; c < 8; c++)
            p2[c] = __ldg(&g_pspX[((size_t)(b * 8 + c) * 64 + t) * 4096 + yx]);
#pragma unroll
        for (int o = 0; o < 2; o++) {
            float z = 0.f;
#pragma unroll
            for (int c = 0; c < 8; c++)
                z = __fmaf_rn(p2[c], w[(c * 2 + o) * 4 + ij], z);
            float R  = __fmul_rn(CC2f, Q[o]);
            float m  = __fadd_rn(z, R);
            float dd = __fadd_rn(m, -50.f);
            float bt = __fmaf_rn(1.2e-7f, __fadd_rn(fabsf(m), fabsf(dd)), Bn[o]);
            bool s;
            if (dd > bt) s = true;
            else if (dd < -bt) s = false;
            else {
                double zd = 0.0;
#pragma unroll 1
                for (int c = 0; c < 8; c++) {
                    u64 sw = g_s1[((b * 8 + c) * 64 + y) * 64 + x];
                    zd = fma((double)w[(c * 2 + o) * 4 + ij],
                             (double)tapsum(sw, d_kB, t), zd);
                }
                s = (zd + (double)refr(h[o], r2s, t) >= 50.0);
            }
            float sf = s ? 1.f : 0.f;
            Q[o] = __fmul_rn(A2f, __fadd_rn(Q[o], P[o]));
            P[o] = __fmaf_rn(A2f, P[o], sf);
            if (s) h[o] |= (1ull << t);
        }
    }
    int i = ij >> 1, j = ij & 1;
#pragma unroll
    for (int o = 0; o < 2; o++)
        g_s2[((b * 2 + o) * 128 + (2 * y + i)) * 128 + (2 * x + j)] = h[o];
}

// ============================================================
// K4a: psp3 via recurrence -> g_pspX [bc2][t][yx16384] (coalesced stores)
// ============================================================
__global__ void k_psp3()
{
    int idx = blockIdx.x * 256 + threadIdx.x;   // 262144 = [b*2+o][yx]
    u64 bits = g_s2[idx];
    int bc = idx >> 14, yx = idx & 16383;
    float* base = g_pspX + (size_t)bc * 64 * 16384 + yx;
    float P = 0.f, Q = 0.f;
#pragma unroll
    for (int t = 0; t < 64; t++) {
        base[(size_t)t * 16384] = __fmul_rn(C4f, Q);
        float s = (float)((unsigned)((bits >> t) & 1ull));
        float tq = __fadd_rn(__fadd_rn(Q, P), s);
        Q = __fmul_rn(A4f, tq);
        P = __fmul_rn(A4f, __fadd_rn(P, s));
    }
}

// ============================================================
// K4b: layer3 conv3x3 — f32 chain + CORRECTED refr recurrence (+32-step tail pair,
//      same corrected form, fed by s[t-32]) + band; exact fallback
// ============================================================
__global__ void __launch_bounds__(256) k_layer3(const float* __restrict__ w3g,
                                                float* __restrict__ out)
{
    __shared__ float w[36], r3s[32];
    if (threadIdx.x < 36) w[threadIdx.x] = w3g[threadIdx.x];
    if (threadIdx.x < 32) r3s[threadIdx.x] = d_r3[threadIdx.x];
    __syncthreads();

    int tid0 = blockIdx.x * 256 + threadIdx.x;  // 131072 threads
    int b = tid0 >> 14, yx = tid0 & 16383;
    int Y = yx >> 7, X = yx & 127;

    float W30 = 0.f, W31 = 0.f;
#pragma unroll
    for (int j = 0; j < 18; j++) { W30 += fabsf(w[j]); W31 += fabsf(w[18 + j]); }
    float Bn[2] = { __fmaf_rn(W30, 1.4e-4f, 0.05f), __fmaf_rn(W31, 1.4e-4f, 0.05f) };

    size_t nb[18];
    bool val[18];
#pragma unroll
    for (int c = 0; c < 2; c++)
#pragma unroll
        for (int ky = 0; ky < 3; ky++)
#pragma unroll
            for (int kx = 0; kx < 3; kx++) {
                int j = c * 9 + ky * 3 + kx;
                int gy = Y + ky - 1, gx = X + kx - 1;
                val[j] = ((unsigned)gy < 128u) && ((unsigned)gx < 128u);
                nb[j] = (size_t)(b * 2 + c) * 64 * 16384 + (size_t)(val[j] ? gy * 128 + gx : 0);
            }

    bool eY = (Y == 0) || (Y == 127);
    bool eX = (X == 0) || (X == 127);
    int y0 = (Y == 0) ? 0 : ((Y - 1) >> 1);
    int y1 = (y0 + 1 > 63) ? 63 : y0 + 1;
    int x0 = (X == 0) ? 0 : ((X - 1) >> 1);
    int x1 = (x0 + 1 > 63) ? 63 : x0 + 1;
    float wy1 = (Y & 1) ? 0.25f : 0.75f, wy0 = 1.f - wy1;
    float wx1 = (X & 1) ? 0.25f : 0.75f, wx0 = 1.f - wx1;

    const float* pr[2][4];
#pragma unroll
    for (int c = 0; c < 2; c++) {
        const float* base = &g_psp1[(size_t)(b * 2 + c) * 64 * 64 * 64];
        pr[c][0] = base + ((size_t)y0 * 64 + x0) * 64;
        pr[c][1] = base + ((size_t)y1 * 64 + x0) * 64;
        pr[c][2] = base + ((size_t)y0 * 64 + x1) * 64;
        pr[c][3] = base + ((size_t)y1 * 64 + x1) * 64;
    }

    u64 h[2] = {0ull, 0ull};
    float P[2] = {0.f, 0.f}, Q[2] = {0.f, 0.f};     // refr main T,S
    float Po[2] = {0.f, 0.f}, Qo[2] = {0.f, 0.f};   // 32-delayed tail T,S

#pragma unroll 1
    for (int t = 0; t < 64; t++) {
        float xv[18];
        size_t toff = (size_t)t * 16384;
#pragma unroll
        for (int j = 0; j < 18; j++)
            xv[j] = val[j] ? __ldg(&g_pspX[nb[j] + toff]) : 0.f;

        float a0 = 0.f, a1 = 0.f;
#pragma unroll
        for (int j = 0; j < 18; j++) {
            a0 = __fmaf_rn(w[j], xv[j], a0);
            a1 = __fmaf_rn(w[18 + j], xv[j], a1);
        }

#pragma unroll
        for (int o = 0; o < 2; o++) {
            float p00 = pr[o][0][t], p10 = pr[o][1][t];
            float p01 = pr[o][2][t], p11 = pr[o][3][t];
            float A  = eY ? p00 : __fmaf_rn(wy1, p10, __fmul_rn(wy0, p00));
            float B2 = eY ? p01 : __fmaf_rn(wy1, p11, __fmul_rn(wy0, p01));
            float skip = eX ? A : __fmaf_rn(wx1, B2, __fmul_rn(wx0, A));
            float tail = __fmaf_rn(32.f, Po[o], Qo[o]);
            float R  = __fmaf_rn(CC3f, Q[o], -__fmul_rn(CT3f, tail));
            float m1 = __fadd_rn((o ? a1 : a0), skip);
            float m  = __fadd_rn(m1, R);
            float dd = __fadd_rn(m, -100.f);
            float bt = __fmaf_rn(1.2e-7f,
                        __fadd_rn(fabsf(m1), __fadd_rn(fabsf(m), fabsf(dd))), Bn[o]);
            bool s;
            if (dd > bt) s = true;
            else if (dd < -bt) s = false;
            else {
                double ad = 0.0;
#pragma unroll 1
                for (int j = 0; j < 18; j++) {
                    int c_ = j / 9, rm_ = j % 9, ky_ = rm_ / 3, kx_ = rm_ % 3;
                    int gy = Y + ky_ - 1, gx = X + kx_ - 1;
                    double xd = 0.0;
                    if ((unsigned)gy < 128u && (unsigned)gx < 128u)
                        xd = (double)tapsum(g_s2[((b * 2 + c_) * 128 + gy) * 128 + gx],
                                            d_kC, t);
                    ad = fma((double)w[o * 18 + j], xd, ad);
                }
                const u64* ibb = &g_inbits[(b * 2 + o) * 4096];
                float e00 = tapsum(ibb[y0 * 64 + x0], d_kA, t);
                float e10 = tapsum(ibb[y1 * 64 + x0], d_kA, t);
                float e01 = tapsum(ibb[y0 * 64 + x1], d_kA, t);
                float e11 = tapsum(ibb[y1 * 64 + x1], d_kA, t);
                float Ae  = eY ? e00 : __fmaf_rn(wy1, e10, __fmul_rn(wy0, e00));
                float Be  = eY ? e01 : __fmaf_rn(wy1, e11, __fmul_rn(wy0, e01));
                float ske = eX ? Ae : __fmaf_rn(wx1, Be, __fmul_rn(wx0, Ae));
                s = (ad + (double)ske + (double)refr(h[o], r3s, t) >= 100.0);
            }
            float sf = s ? 1.f : 0.f;
            float so = (t >= 32) ? (float)((unsigned)((h[o] >> (t - 32)) & 1ull)) : 0.f;
            Q[o] = __fmul_rn(A4f, __fadd_rn(Q[o], P[o]));
            P[o] = __fmaf_rn(A4f, P[o], sf);
            Qo[o] = __fmul_rn(A4f, __fadd_rn(Qo[o], Po[o]));
            Po[o] = __fmaf_rn(A4f, Po[o], so);
            if (s) h[o] |= (1ull << t);
        }
    }

#pragma unroll
    for (int o = 0; o < 2; o++) {
        float4* dst = (float4*)(out + ((size_t)((b * 2 + o) * 128 + Y) * 128 + X) * 64);
        u64 m = h[o];
#pragma unroll
        for (int k = 0; k < 16; k++) {
            float4 v;
            v.x = (float)((unsigned)((m >> (4 * k + 0)) & 1ull));
            v.y = (float)((unsigned)((m >> (4 * k + 1)) & 1ull));
            v.z = (float)((unsigned)((m >> (4 * k + 2)) & 1ull));
            v.w = (float)((unsigned)((m >> (4 * k + 3)) & 1ull));
            dst[k] = v;
        }
    }
}

extern "C" void kernel_launch(void* const* d_in, const int* in_sizes, int n_in,
                              void* d_out, int out_size)
{
    const float* in = (const float*)d_in[0];
    const float* w1 = (const float*)d_in[1];
    const float* w2 = (const float*)d_in[2];
    const float* w3 = (const float*)d_in[3];
    float* out = (float*)d_out;

    cudaFuncSetAttribute(k_layer1, cudaFuncAttributeMaxDynamicSharedMemorySize,
                         2 * 144 * TPAD * 4);

    k_init<<<1, 64>>>();
    k_psp1<<<256, 256>>>(in);
    dim3 g1(8, 8, 8);
    k_layer1<<<g1, 256, 2 * 144 * TPAD * 4>>>(w1);
    k_psp2<<<1024, 256>>>();
    k_layer2<<<512, 256>>>(w2);
    k_psp3<<<1024, 256>>>();
    k_layer3<<<512, 256>>>(w3, out);
}